// round 12
// baseline (speedup 1.0000x reference)
#include <cuda_runtime.h>
#include <cuda_fp16.h>
#include <math.h>
#include <stdint.h>

#define BB 2
#define TT 2048
#define HH 1024
#define NHH 16
#define DD 64
#define FFF 4096
#define LL 6
#define MM (BB*TT)
#define H3 (3*HH)

typedef __half fp16;

// ---------------- device-global scratch ------------------------------------
__device__ float g_x [MM*HH];
__device__ fp16  g_xh[MM*HH];
__device__ fp16  g_qkvh[MM*H3];
__device__ fp16  g_oh[MM*HH];
__device__ float g_t [MM*HH];
__device__ fp16  g_hh[MM*FFF];
__device__ fp16  w_qkv_h[LL*H3*HH];
__device__ fp16  w_p_h  [LL*HH*HH];
__device__ fp16  w_1_h  [LL*FFF*HH];
__device__ fp16  w_2_h  [LL*HH*FFF];
__device__ float g_bqkv[LL*H3];

// ---------------- helpers ---------------------------------------------------
__device__ __forceinline__ uint32_t packh2(fp16 a, fp16 b) {
    return (uint32_t)__half_as_ushort(a) | ((uint32_t)__half_as_ushort(b) << 16);
}
__device__ __forceinline__ uint32_t smem_u32(const void* p) {
    return (uint32_t)__cvta_generic_to_shared(p);
}
__device__ __forceinline__ void cp16(uint32_t s, const void* g) {
    asm volatile("cp.async.cg.shared.global [%0],[%1],16;\n" :: "r"(s), "l"(g));
}
__device__ __forceinline__ void ldmx4(uint32_t& r0, uint32_t& r1, uint32_t& r2,
                                      uint32_t& r3, uint32_t addr) {
    asm volatile("ldmatrix.sync.aligned.m8n8.x4.shared.b16 {%0,%1,%2,%3},[%4];\n"
                 : "=r"(r0), "=r"(r1), "=r"(r2), "=r"(r3) : "r"(addr));
}
__device__ __forceinline__ void ldmx4t(uint32_t& r0, uint32_t& r1, uint32_t& r2,
                                       uint32_t& r3, uint32_t addr) {
    asm volatile("ldmatrix.sync.aligned.m8n8.x4.trans.shared.b16 {%0,%1,%2,%3},[%4];\n"
                 : "=r"(r0), "=r"(r1), "=r"(r2), "=r"(r3) : "r"(addr));
}
__device__ __forceinline__ void mma16816(float c[4], uint32_t a0, uint32_t a1,
                                         uint32_t a2, uint32_t a3,
                                         uint32_t b0, uint32_t b1) {
    asm volatile(
        "mma.sync.aligned.m16n8k16.row.col.f32.f16.f16.f32 "
        "{%0,%1,%2,%3}, {%4,%5,%6,%7}, {%8,%9}, {%0,%1,%2,%3};"
        : "+f"(c[0]), "+f"(c[1]), "+f"(c[2]), "+f"(c[3])
        : "r"(a0), "r"(a1), "r"(a2), "r"(a3), "r"(b0), "r"(b1));
}

// FMA-pipe e^x, degree-3 (result feeds fp16 P; rel err ~2e-4 is below fp16 ulp).
__device__ __forceinline__ float fexp(float x) {
    x = fmaxf(x, -87.0f);
    const float L2E = 1.4426950408889634f;
    float t = fmaf(x, L2E, 12582912.0f);
    float i = t - 12582912.0f;
    float f = fmaf(x, L2E, -i);
    float p =            5.550357e-2f;
    p = fmaf(p, f, 2.402291e-1f);
    p = fmaf(p, f, 6.931406e-1f);
    p = fmaf(p, f, 1.0f);
    int eb = (__float_as_int(t) - 0x4B400000 + 127) << 23;
    return __int_as_float(eb) * p;
}

// ---------------- single fused weight transpose (fp16) ----------------------
#define QKV_TILES 18432
#define WP_END    24576
#define W1_END    49152
#define TOT_TILES 73728

__global__ __launch_bounds__(256) void wsplit_all(
    const float* __restrict__ Wq, const float* __restrict__ Wk,
    const float* __restrict__ Wv, const float* __restrict__ Wp,
    const float* __restrict__ W1, const float* __restrict__ W2)
{
    __shared__ float tbuf[32][33];
    const int t = blockIdx.x;
    const float* src; fp16 *dh;
    int K, N, n0, k0;
    if (t < QKV_TILES) {
        int z = t >> 10, r = t & 1023;
        int l = z / 3, wch = z % 3;
        src = (wch == 0 ? Wq : wch == 1 ? Wk : Wv) + (size_t)l * HH * HH;
        dh = w_qkv_h + (size_t)l * H3 * HH + (size_t)wch * HH * HH;
        K = HH; N = HH; n0 = (r & 31) * 32; k0 = (r >> 5) * 32;
    } else if (t < WP_END) {
        int t2 = t - QKV_TILES; int l = t2 >> 10, r = t2 & 1023;
        src = Wp + (size_t)l * HH * HH;
        dh = w_p_h + (size_t)l * HH * HH;
        K = HH; N = HH; n0 = (r & 31) * 32; k0 = (r >> 5) * 32;
    } else if (t < W1_END) {
        int t3 = t - WP_END; int l = t3 >> 12, r = t3 & 4095;
        src = W1 + (size_t)l * HH * FFF;
        dh = w_1_h + (size_t)l * FFF * HH;
        K = HH; N = FFF; n0 = (r & 127) * 32; k0 = (r >> 7) * 32;
    } else {
        int t4 = t - W1_END; int l = t4 >> 12, r = t4 & 4095;
        src = W2 + (size_t)l * FFF * HH;
        dh = w_2_h + (size_t)l * HH * FFF;
        K = FFF; N = HH; n0 = (r & 31) * 32; k0 = (r >> 5) * 32;
    }

    const int tx = threadIdx.x & 31, ty = threadIdx.x >> 5;
    #pragma unroll
    for (int u = 0; u < 4; u++)
        tbuf[ty + u * 8][tx] = src[(size_t)(k0 + ty + u * 8) * N + n0 + tx];
    __syncthreads();
    #pragma unroll
    for (int u = 0; u < 4; u++) {
        size_t o = (size_t)(n0 + ty + u * 8) * K + k0 + tx;
        dh[o] = __float2half_rn(tbuf[tx][ty + u * 8]);
    }
}

__global__ void prep_kernel(const float* __restrict__ in,
                            const float* bq, const float* bk, const float* bv)
{
    int id = blockIdx.x * blockDim.x + threadIdx.x;
    if (id < LL * H3) {
        int l = id / H3, c = id % H3;
        g_bqkv[id] = (c < HH) ? bq[l*HH + c]
                   : (c < 2*HH) ? bk[l*HH + c - HH] : bv[l*HH + c - 2*HH];
    }
    if (id < MM*HH/4) {
        float4 v = *(const float4*)(in + (size_t)id * 4);
        *(float4*)(g_x + (size_t)id * 4) = v;
        *(uint2*)(g_xh + (size_t)id * 4) =
            make_uint2(packh2(__float2half_rn(v.x), __float2half_rn(v.y)),
                       packh2(__float2half_rn(v.z), __float2half_rn(v.w)));
    }
}

// ---------------- GEMM (fp16, BK=64, 128 thr, warp tile 64x64) ---------------
// epi: 1 bias+gelu->hi, 2 bias+resid->f32, 3 bias->hi
#define BK 64
#define SUBB 16384
#define STAGE_B (2*SUBB)           // Ah Bh = 32 KB
#define GEMM_SMEM (3*STAGE_B)      // 96 KB

__device__ __forceinline__ uint32_t swz(int r, int c) {   // c = 16B chunk 0..7
    return (uint32_t)(r * 128 + ((c ^ (r & 7)) << 4));
}

__device__ __forceinline__ void ld_stage(
    uint32_t st, const fp16* Agh, const fp16* Bgh,
    int bm, int bn, int K, int k0, int tid)
{
    #pragma unroll
    for (int u = tid; u < 1024; u += 128) {
        const int r = u >> 3, c = u & 7;
        const uint32_t sw = swz(r, c);
        cp16(st + sw,         Agh + (size_t)(bm + r) * K + k0 + c * 8);
        cp16(st + SUBB + sw,  Bgh + (size_t)(bn + r) * K + k0 + c * 8);
    }
}

__global__ __launch_bounds__(128, 2) void gemm_kernel(
    const fp16* __restrict__ Agh, const fp16* __restrict__ Bgh,
    const float* __restrict__ bias, const float* __restrict__ resid,
    float* __restrict__ C, fp16* __restrict__ Ch,
    int M, int N, int K, int epi)
{
    extern __shared__ __align__(16) fp16 sm[];
    const int tid  = threadIdx.x;
    const int lane = tid & 31;
    const int wid  = tid >> 5;        // 0..3
    const int warp_m = wid & 1;       // 2 x 64 rows
    const int warp_n = wid >> 1;      // 2 x 64 cols
    const int bm = blockIdx.y * 128;
    const int bn = blockIdx.x * 128;
    const uint32_t smB = smem_u32(sm);

    float acc[4][8][4];
    #pragma unroll
    for (int i = 0; i < 4; i++)
        #pragma unroll
        for (int j = 0; j < 8; j++)
            #pragma unroll
            for (int u = 0; u < 4; u++) acc[i][j][u] = 0.f;

    const int ntiles = K / BK;

    ld_stage(smB, Agh, Bgh, bm, bn, K, 0, tid);
    asm volatile("cp.async.commit_group;\n");
    if (ntiles > 1)
        ld_stage(smB + STAGE_B, Agh, Bgh, bm, bn, K, BK, tid);
    asm volatile("cp.async.commit_group;\n");

    const int lr = lane & 15, lc = lane >> 4;

    for (int kt = 0; kt < ntiles; kt++) {
        asm volatile("cp.async.wait_group 1;\n");
        __syncthreads();

        const int nx = kt + 2;
        if (nx < ntiles)
            ld_stage(smB + (nx % 3) * STAGE_B, Agh, Bgh, bm, bn, K, nx * BK, tid);
        asm volatile("cp.async.commit_group;\n");

        const uint32_t st = smB + (kt % 3) * STAGE_B;
        const uint32_t Ah = st;
        const uint32_t Bh = st + SUBB;

        #pragma unroll
        for (int kk = 0; kk < 4; kk++) {
            const int cch = kk * 2 + lc;
            uint32_t a[4][4], bh[8][2];
            #pragma unroll
            for (int i = 0; i < 4; i++) {
                const int r_ = warp_m*64 + i*16 + lr;
                ldmx4(a[i][0], a[i][1], a[i][2], a[i][3], Ah + swz(r_, cch));
            }
            #pragma unroll
            for (int j16 = 0; j16 < 4; j16++) {
                const int rb_ = warp_n*64 + j16*16 + lr;
                uint32_t r0, r1, r2, r3;
                ldmx4(r0, r1, r2, r3, Bh + swz(rb_, cch));
                bh[j16*2][0] = r0; bh[j16*2][1] = r2;
                bh[j16*2+1][0] = r1; bh[j16*2+1][1] = r3;
            }
            #pragma unroll
            for (int i = 0; i < 4; i++)
                #pragma unroll
                for (int j = 0; j < 8; j++)
                    mma16816(acc[i][j], a[i][0],a[i][1],a[i][2],a[i][3], bh[j][0],bh[j][1]);
        }
    }

    #pragma unroll
    for (int i = 0; i < 4; i++) {
        #pragma unroll
        for (int j = 0; j < 8; j++) {
            const int row0 = bm + warp_m*64 + i*16 + (lane >> 2);
            const int col  = bn + warp_n*64 + j*8 + 2*(lane & 3);
            const float2 bv = *(const float2*)(bias + col);
            #pragma unroll
            for (int half_ = 0; half_ < 2; half_++) {
                const int row = row0 + half_ * 8;
                float rx = acc[i][j][half_*2+0] + bv.x;
                float ry = acc[i][j][half_*2+1] + bv.y;
                if (epi == 1) {
                    rx = 0.5f * rx * (1.0f + erff(rx * 0.70710678118654752f));
                    ry = 0.5f * ry * (1.0f + erff(ry * 0.70710678118654752f));
                    *(uint32_t*)(Ch + (size_t)row*N + col) =
                        packh2(__float2half_rn(rx), __float2half_rn(ry));
                } else if (epi == 2) {
                    const float2 rv = *(const float2*)(resid + (size_t)row*N + col);
                    *(float2*)(C + (size_t)row*N + col) = make_float2(rx + rv.x, ry + rv.y);
                } else {
                    *(uint32_t*)(Ch + (size_t)row*N + col) =
                        packh2(__float2half_rn(rx), __float2half_rn(ry));
                }
            }
        }
    }
}

// ---------------- causal flash attention -------------------------------------
// 128-query blocks (8 warps x 16q), 64-k tiles, double-buffered K/V.
#define AT_LDT 72
#define AQ_BYTES (128*AT_LDT*2)
#define AKV_BYTES (64*AT_LDT*2)
#define ATT_SMEM (AQ_BYTES + 4*AKV_BYTES)

__global__ __launch_bounds__(256, 2) void attn_kernel(const fp16* __restrict__ QKVh)
{
    extern __shared__ __align__(16) fp16 asmem[];
    const uint32_t sQ  = smem_u32(asmem);
    const uint32_t sK0 = sQ + AQ_BYTES;
    const uint32_t sV0 = sQ + AQ_BYTES + 2*AKV_BYTES;

    const int h   = blockIdx.y;
    const int b   = blockIdx.z;
    const int tid = threadIdx.x;
    const int w    = tid >> 5;
    const int lane = tid & 31;
    const int lr = lane & 15, lc = lane >> 4;
    const int rr = lane >> 2, cq = lane & 3;

    #pragma unroll 1
    for (int ph_ = 0; ph_ < 2; ph_++) {
        const int qtp = ph_ ? (TT/128 - 1 - blockIdx.x) : blockIdx.x;
        const int qb  = qtp * 128;
        const int nkt = 2 * qtp + 2;

        #pragma unroll
        for (int c = tid; c < 1024; c += 256) {
            int row = c >> 3, seg = c & 7;
            size_t g = ((size_t)(b*TT + qb + row))*H3 + h*DD + seg*8;
            cp16(sQ + (uint32_t)(row*AT_LDT + seg*8)*2, QKVh + g);
        }
        #pragma unroll
        for (int c = tid; c < 512; c += 256) {
            int row = c >> 3, seg = c & 7;
            size_t gk = ((size_t)(b*TT + row))*H3 + HH + h*DD + seg*8;
            uint32_t s = (uint32_t)(row*AT_LDT + seg*8)*2;
            cp16(sK0 + s, QKVh + gk);
            cp16(sV0 + s, QKVh + gk + HH);
        }
        asm volatile("cp.async.commit_group;\n");

        float O[8][4];
        #pragma unroll
        for (int j = 0; j < 8; j++)
            #pragma unroll
            for (int u = 0; u < 4; u++) O[j][u] = 0.f;
        float m0 = -1e30f, m1 = -1e30f, l0 = 0.f, l1 = 0.f;

        for (int kt = 0; kt < nkt; kt++) {
            if (kt + 1 < nkt) {
                const uint32_t sKp = sK0 + ((kt + 1) & 1) * AKV_BYTES;
                const uint32_t sVp = sV0 + ((kt + 1) & 1) * AKV_BYTES;
                #pragma unroll
                for (int c = tid; c < 512; c += 256) {
                    int row = c >> 3, seg = c & 7;
                    size_t gk = ((size_t)(b*TT + (kt+1)*64 + row))*H3 + HH + h*DD + seg*8;
                    uint32_t s = (uint32_t)(row*AT_LDT + seg*8)*2;
                    cp16(sKp + s, QKVh + gk);
                    cp16(sVp + s, QKVh + gk + HH);
                }
            }
            asm volatile("cp.async.commit_group;\n");
            asm volatile("cp.async.wait_group 1;\n");
            __syncthreads();

            const bool active = (kt * 64 <= qb + w*16 + 15);
            if (active) {
                const uint32_t sK = sK0 + (kt & 1) * AKV_BYTES;
                const uint32_t sV = sV0 + (kt & 1) * AKV_BYTES;

                float S[8][4];
                #pragma unroll
                for (int j = 0; j < 8; j++)
                    #pragma unroll
                    for (int u = 0; u < 4; u++) S[j][u] = 0.f;

                #pragma unroll
                for (int ks = 0; ks < 4; ks++) {
                    const uint32_t coff = (uint32_t)(ks*16 + lc*8)*2;
                    uint32_t qh[4];
                    ldmx4(qh[0], qh[1], qh[2], qh[3],
                          sQ + (uint32_t)((w*16 + lr)*AT_LDT)*2 + coff);
                    #pragma unroll
                    for (int j16 = 0; j16 < 4; j16++) {
                        uint32_t rb = (uint32_t)((j16*16 + lr)*AT_LDT)*2 + coff;
                        uint32_t k0,k1,k2,k3;
                        ldmx4(k0,k1,k2,k3, sK + rb);
                        mma16816(S[j16*2],   qh[0],qh[1],qh[2],qh[3], k0,k2);
                        mma16816(S[j16*2+1], qh[0],qh[1],qh[2],qh[3], k1,k3);
                    }
                }

                #pragma unroll
                for (int j = 0; j < 8; j++)
                    #pragma unroll
                    for (int u = 0; u < 4; u++) S[j][u] *= 0.125f;

                if (kt*64 + 63 > qb + w*16) {
                    const int q0 = qb + w*16 + rr, q1 = q0 + 8;
                    #pragma unroll
                    for (int j = 0; j < 8; j++) {
                        const int c0 = kt*64 + 8*j + 2*cq, c1 = c0 + 1;
                        if (c0 > q0) S[j][0] = -1e30f;
                        if (c1 > q0) S[j][1] = -1e30f;
                        if (c0 > q1) S[j][2] = -1e30f;
                        if (c1 > q1) S[j][3] = -1e30f;
                    }
                }

                float t0 = -1e30f, t1 = -1e30f;
                #pragma unroll
                for (int j = 0; j < 8; j++) {
                    t0 = fmaxf(t0, fmaxf(S[j][0], S[j][1]));
                    t1 = fmaxf(t1, fmaxf(S[j][2], S[j][3]));
                }
                t0 = fmaxf(t0, __shfl_xor_sync(0xffffffffu, t0, 1));
                t0 = fmaxf(t0, __shfl_xor_sync(0xffffffffu, t0, 2));
                t1 = fmaxf(t1, __shfl_xor_sync(0xffffffffu, t1, 1));
                t1 = fmaxf(t1, __shfl_xor_sync(0xffffffffu, t1, 2));

                const float n0 = fmaxf(m0, t0), n1 = fmaxf(m1, t1);
                const float f0 = fexp(m0 - n0), f1 = fexp(m1 - n1);
                m0 = n0; m1 = n1;

                uint32_t ph2[8][2];
                float s0 = 0.f, s1 = 0.f;
                #pragma unroll
                for (int j = 0; j < 8; j++) {
                    float p0 = fexp(S[j][0] - n0), p1 = fexp(S[j][1] - n0);
                    float p2 = fexp(S[j][2] - n1), p3 = fexp(S[j][3] - n1);
                    s0 += p0 + p1; s1 += p2 + p3;
                    ph2[j][0] = packh2(__float2half_rn(p0), __float2half_rn(p1));
                    ph2[j][1] = packh2(__float2half_rn(p2), __float2half_rn(p3));
                }
                s0 += __shfl_xor_sync(0xffffffffu, s0, 1);
                s0 += __shfl_xor_sync(0xffffffffu, s0, 2);
                s1 += __shfl_xor_sync(0xffffffffu, s1, 1);
                s1 += __shfl_xor_sync(0xffffffffu, s1, 2);
                l0 = l0*f0 + s0; l1 = l1*f1 + s1;

                #pragma unroll
                for (int j = 0; j < 8; j++) {
                    O[j][0] *= f0; O[j][1] *= f0; O[j][2] *= f1; O[j][3] *= f1;
                }

                #pragma unroll
                for (int ks = 0; ks < 4; ks++) {
                    uint32_t a0 = ph2[2*ks][0], a1 = ph2[2*ks][1],
                             a2 = ph2[2*ks+1][0], a3 = ph2[2*ks+1][1];
                    #pragma unroll
                    for (int j16 = 0; j16 < 4; j16++) {
                        uint32_t rbv = (uint32_t)((ks*16 + lr)*AT_LDT + j16*16 + lc*8)*2;
                        uint32_t v0,v1,v2,v3;
                        ldmx4t(v0,v1,v2,v3, sV + rbv);
                        mma16816(O[2*j16],   a0,a1,a2,a3, v0,v1);
                        mma16816(O[2*j16+1], a0,a1,a2,a3, v2,v3);
                    }
                }
            }
            __syncthreads();
        }

        const float inv0 = 1.f / l0, inv1 = 1.f / l1;
        const size_t row0 = (size_t)(b*TT + qb + w*16 + rr);
        const size_t row1 = row0 + 8;
        #pragma unroll
        for (int j = 0; j < 8; j++) {
            const int col = h*DD + 8*j + 2*cq;
            *(uint32_t*)(g_oh + row0*HH + col) =
                packh2(__float2half_rn(O[j][0]*inv0), __float2half_rn(O[j][1]*inv0));
            *(uint32_t*)(g_oh + row1*HH + col) =
                packh2(__float2half_rn(O[j][2]*inv1), __float2half_rn(O[j][3]*inv1));
        }
        __syncthreads();
    }
}

// ---------------- LayerNorm (warp-shuffle reduction) -------------------------
__global__ __launch_bounds__(256) void ln_kernel(
    const float* __restrict__ in, const float* __restrict__ gamma,
    const float* __restrict__ beta, float* __restrict__ out,
    fp16* __restrict__ outh)
{
    __shared__ float ws[8], ws2[8];
    const int row = blockIdx.x;
    const int tid = threadIdx.x;
    const int lane = tid & 31, wid = tid >> 5;
    const float* p = in + (size_t)row * HH;

    float4 v = *(const float4*)(p + tid * 4);
    float s = v.x + v.y + v.z + v.w;
    float q = v.x*v.x + v.y*v.y + v.z*v.z + v.w*v.w;
    #pragma unroll
    for (int off = 16; off > 0; off >>= 1) {
        s += __shfl_xor_sync(0xffffffffu, s, off);
        q += __shfl_xor_sync(0xffffffffu, q, off);
    }
    if (lane == 0) { ws[wid] = s; ws2[wid] = q; }
    __syncthreads();
    float ts = 0.f, tq = 0.f;
    #pragma unroll
    for (int u = 0; u < 8; u++) { ts += ws[u]; tq += ws2[u]; }
    const float mean = ts * (1.0f / HH);
    const float var  = tq * (1.0f / HH) - mean * mean;
    const float rstd = rsqrtf(var + 1e-5f);

    float dx = v.x-mean, dy = v.y-mean, dz = v.z-mean, dw = v.w-mean;
    float4 g  = *(const float4*)(gamma + tid * 4);
    float4 be = *(const float4*)(beta + tid * 4);
    float4 rr;
    rr.x = dx*rstd*g.x + be.x;
    rr.y = dy*rstd*g.y + be.y;
    rr.z = dz*rstd*g.z + be.z;
    rr.w = dw*rstd*g.w + be.w;
    *(float4*)(out + (size_t)row*HH + tid*4) = rr;
    *(uint2*)(outh + (size_t)row*HH + tid*4) =
        make_uint2(packh2(__float2half_rn(rr.x), __float2half_rn(rr.y)),
                   packh2(__float2half_rn(rr.z), __float2half_rn(rr.w)));
}

// ---------------- launcher -------------------------------------------------
extern "C" void kernel_launch(void* const* d_in, const int* in_sizes, int n_in,
                              void* d_out, int out_size)
{
    const float* Wq  = (const float*)d_in[1];
    const float* bq  = (const float*)d_in[2];
    const float* Wk  = (const float*)d_in[3];
    const float* bk  = (const float*)d_in[4];
    const float* Wv  = (const float*)d_in[5];
    const float* bv  = (const float*)d_in[6];
    const float* Wp  = (const float*)d_in[7];
    const float* bp  = (const float*)d_in[8];
    const float* W1  = (const float*)d_in[9];
    const float* b1  = (const float*)d_in[10];
    const float* W2  = (const float*)d_in[11];
    const float* b2  = (const float*)d_in[12];
    const float* g1w = (const float*)d_in[13];
    const float* be1 = (const float*)d_in[14];
    const float* g2w = (const float*)d_in[15];
    const float* be2 = (const float*)d_in[16];

    cudaFuncSetAttribute(gemm_kernel, cudaFuncAttributeMaxDynamicSharedMemorySize, GEMM_SMEM);
    cudaFuncSetAttribute(attn_kernel, cudaFuncAttributeMaxDynamicSharedMemorySize, ATT_SMEM);

    float *gx, *gt, *gbqkv;
    fp16 *gxh, *gqkvh, *goh, *ghh;
    fp16 *wqh, *wph, *w1h, *w2h;
    cudaGetSymbolAddress((void**)&gx,    g_x);
    cudaGetSymbolAddress((void**)&gxh,   g_xh);
    cudaGetSymbolAddress((void**)&gqkvh, g_qkvh);
    cudaGetSymbolAddress((void**)&goh,   g_oh);
    cudaGetSymbolAddress((void**)&gt,    g_t);
    cudaGetSymbolAddress((void**)&ghh,   g_hh);
    cudaGetSymbolAddress((void**)&wqh,   w_qkv_h);
    cudaGetSymbolAddress((void**)&wph,   w_p_h);
    cudaGetSymbolAddress((void**)&w1h,   w_1_h);
    cudaGetSymbolAddress((void**)&w2h,   w_2_h);
    cudaGetSymbolAddress((void**)&gbqkv, g_bqkv);

    wsplit_all<<<TOT_TILES, 256>>>(Wq, Wk, Wv, Wp, W1, W2);
    prep_kernel<<<(MM*HH/4 + 255)/256, 256>>>((const float*)d_in[0], bq, bk, bv);

    const dim3 gridQKV(H3/128, MM/128);   // (24, 32)
    const dim3 gridH(HH/128, MM/128);     // (8, 32)
    const dim3 gridF(FFF/128, MM/128);    // (32, 32)
    const dim3 gridA(TT/256, NHH, BB);    // paired 128q-tiles: (8, 16, 2)

    for (int l = 0; l < LL; l++) {
        const size_t bo = (size_t)l * HH;

        gemm_kernel<<<gridQKV, 128, GEMM_SMEM>>>(
            gxh, wqh + (size_t)l*H3*HH,
            gbqkv + (size_t)l*H3, nullptr, nullptr, gqkvh,
            MM, H3, HH, 3);

        attn_kernel<<<gridA, 256, ATT_SMEM>>>(gqkvh);

        gemm_kernel<<<gridH, 128, GEMM_SMEM>>>(
            goh, wph + (size_t)l*HH*HH,
            bp + bo, gx, gt, nullptr, MM, HH, HH, 2);
        ln_kernel<<<MM, 256>>>(gt, g1w + bo, be1 + bo, gx, gxh);

        gemm_kernel<<<gridF, 128, GEMM_SMEM>>>(
            gxh, w1h + (size_t)l*FFF*HH,
            b1 + (size_t)l*FFF, nullptr, nullptr, ghh, MM, FFF, HH, 1);
        gemm_kernel<<<gridH, 128, GEMM_SMEM>>>(
            ghh, w2h + (size_t)l*HH*FFF,
            b2 + bo, gx, gt, nullptr, MM, HH, FFF, 2);
        ln_kernel<<<MM, 256>>>(gt, g2w + bo, be2 + bo, gx, gxh);
    }

    cudaMemcpyAsync(d_out, gx, (size_t)MM*HH*sizeof(float),
                    cudaMemcpyDeviceToDevice, 0);
}

// round 13
// speedup vs baseline: 1.4956x; 1.4956x over previous
#include <cuda_runtime.h>
#include <cuda_fp16.h>
#include <math.h>
#include <stdint.h>

#define BB 2
#define TT 2048
#define HH 1024
#define NHH 16
#define DD 64
#define FFF 4096
#define LL 6
#define MM (BB*TT)
#define H3 (3*HH)

typedef __half fp16;

// ---------------- device-global scratch ------------------------------------
__device__ float g_x [MM*HH];
__device__ fp16  g_xh[MM*HH];
__device__ fp16  g_qkvh[MM*H3];
__device__ fp16  g_oh[MM*HH];
__device__ float g_t [MM*HH];
__device__ fp16  g_hh[MM*FFF];
__device__ fp16  w_qkv_h[LL*H3*HH];
__device__ fp16  w_p_h  [LL*HH*HH];
__device__ fp16  w_1_h  [LL*FFF*HH];
__device__ fp16  w_2_h  [LL*HH*FFF];
__device__ float g_bqkv[LL*H3];

// ---------------- helpers ---------------------------------------------------
__device__ __forceinline__ uint32_t packh2(fp16 a, fp16 b) {
    return (uint32_t)__half_as_ushort(a) | ((uint32_t)__half_as_ushort(b) << 16);
}
__device__ __forceinline__ uint32_t smem_u32(const void* p) {
    return (uint32_t)__cvta_generic_to_shared(p);
}
__device__ __forceinline__ void cp16(uint32_t s, const void* g) {
    asm volatile("cp.async.cg.shared.global [%0],[%1],16;\n" :: "r"(s), "l"(g));
}
__device__ __forceinline__ void ldmx4(uint32_t& r0, uint32_t& r1, uint32_t& r2,
                                      uint32_t& r3, uint32_t addr) {
    asm volatile("ldmatrix.sync.aligned.m8n8.x4.shared.b16 {%0,%1,%2,%3},[%4];\n"
                 : "=r"(r0), "=r"(r1), "=r"(r2), "=r"(r3) : "r"(addr));
}
__device__ __forceinline__ void ldmx4t(uint32_t& r0, uint32_t& r1, uint32_t& r2,
                                       uint32_t& r3, uint32_t addr) {
    asm volatile("ldmatrix.sync.aligned.m8n8.x4.trans.shared.b16 {%0,%1,%2,%3},[%4];\n"
                 : "=r"(r0), "=r"(r1), "=r"(r2), "=r"(r3) : "r"(addr));
}
__device__ __forceinline__ void mma16816(float c[4], uint32_t a0, uint32_t a1,
                                         uint32_t a2, uint32_t a3,
                                         uint32_t b0, uint32_t b1) {
    asm volatile(
        "mma.sync.aligned.m16n8k16.row.col.f32.f16.f16.f32 "
        "{%0,%1,%2,%3}, {%4,%5,%6,%7}, {%8,%9}, {%0,%1,%2,%3};"
        : "+f"(c[0]), "+f"(c[1]), "+f"(c[2]), "+f"(c[3])
        : "r"(a0), "r"(a1), "r"(a2), "r"(a3), "r"(b0), "r"(b1));
}

// FMA-pipe e^x, degree-3 (result feeds fp16 P; rel err ~2e-4 < fp16 ulp).
__device__ __forceinline__ float fexp(float x) {
    x = fmaxf(x, -87.0f);
    const float L2E = 1.4426950408889634f;
    float t = fmaf(x, L2E, 12582912.0f);
    float i = t - 12582912.0f;
    float f = fmaf(x, L2E, -i);
    float p =            5.550357e-2f;
    p = fmaf(p, f, 2.402291e-1f);
    p = fmaf(p, f, 6.931406e-1f);
    p = fmaf(p, f, 1.0f);
    int eb = (__float_as_int(t) - 0x4B400000 + 127) << 23;
    return __int_as_float(eb) * p;
}

// ---------------- single fused weight transpose (fp16) ----------------------
#define QKV_TILES 18432
#define WP_END    24576
#define W1_END    49152
#define TOT_TILES 73728

__global__ __launch_bounds__(256) void wsplit_all(
    const float* __restrict__ Wq, const float* __restrict__ Wk,
    const float* __restrict__ Wv, const float* __restrict__ Wp,
    const float* __restrict__ W1, const float* __restrict__ W2)
{
    __shared__ float tbuf[32][33];
    const int t = blockIdx.x;
    const float* src; fp16 *dh;
    int K, N, n0, k0;
    if (t < QKV_TILES) {
        int z = t >> 10, r = t & 1023;
        int l = z / 3, wch = z % 3;
        src = (wch == 0 ? Wq : wch == 1 ? Wk : Wv) + (size_t)l * HH * HH;
        dh = w_qkv_h + (size_t)l * H3 * HH + (size_t)wch * HH * HH;
        K = HH; N = HH; n0 = (r & 31) * 32; k0 = (r >> 5) * 32;
    } else if (t < WP_END) {
        int t2 = t - QKV_TILES; int l = t2 >> 10, r = t2 & 1023;
        src = Wp + (size_t)l * HH * HH;
        dh = w_p_h + (size_t)l * HH * HH;
        K = HH; N = HH; n0 = (r & 31) * 32; k0 = (r >> 5) * 32;
    } else if (t < W1_END) {
        int t3 = t - WP_END; int l = t3 >> 12, r = t3 & 4095;
        src = W1 + (size_t)l * HH * FFF;
        dh = w_1_h + (size_t)l * FFF * HH;
        K = HH; N = FFF; n0 = (r & 127) * 32; k0 = (r >> 7) * 32;
    } else {
        int t4 = t - W1_END; int l = t4 >> 12, r = t4 & 4095;
        src = W2 + (size_t)l * FFF * HH;
        dh = w_2_h + (size_t)l * HH * FFF;
        K = FFF; N = HH; n0 = (r & 31) * 32; k0 = (r >> 5) * 32;
    }

    const int tx = threadIdx.x & 31, ty = threadIdx.x >> 5;
    #pragma unroll
    for (int u = 0; u < 4; u++)
        tbuf[ty + u * 8][tx] = src[(size_t)(k0 + ty + u * 8) * N + n0 + tx];
    __syncthreads();
    #pragma unroll
    for (int u = 0; u < 4; u++) {
        size_t o = (size_t)(n0 + ty + u * 8) * K + k0 + tx;
        dh[o] = __float2half_rn(tbuf[tx][ty + u * 8]);
    }
}

__global__ void prep_kernel(const float* __restrict__ in,
                            const float* bq, const float* bk, const float* bv)
{
    int id = blockIdx.x * blockDim.x + threadIdx.x;
    if (id < LL * H3) {
        int l = id / H3, c = id % H3;
        g_bqkv[id] = (c < HH) ? bq[l*HH + c]
                   : (c < 2*HH) ? bk[l*HH + c - HH] : bv[l*HH + c - 2*HH];
    }
    if (id < MM*HH/4) {
        float4 v = *(const float4*)(in + (size_t)id * 4);
        *(float4*)(g_x + (size_t)id * 4) = v;
        *(uint2*)(g_xh + (size_t)id * 4) =
            make_uint2(packh2(__float2half_rn(v.x), __float2half_rn(v.y)),
                       packh2(__float2half_rn(v.z), __float2half_rn(v.w)));
    }
}

// ---------------- GEMM (fp16 1-term, BK=64, 256 thr, warp tile 64x32) --------
// epi: 1 bias+gelu->hi, 2 bias+resid->f32, 3 bias->hi
#define BK 64
#define SUBB 16384
#define STAGE_B (2*SUBB)           // Ah Bh = 32 KB
#define GEMM_SMEM (3*STAGE_B)      // 96 KB

__device__ __forceinline__ uint32_t swz(int r, int c) {   // c = 16B chunk 0..7
    return (uint32_t)(r * 128 + ((c ^ (r & 7)) << 4));
}

__device__ __forceinline__ void ld_stage(
    uint32_t st, const fp16* Agh, const fp16* Bgh,
    int bm, int bn, int K, int k0, int tid)
{
    #pragma unroll
    for (int u = tid; u < 1024; u += 256) {
        const int r = u >> 3, c = u & 7;
        const uint32_t sw = swz(r, c);
        cp16(st + sw,         Agh + (size_t)(bm + r) * K + k0 + c * 8);
        cp16(st + SUBB + sw,  Bgh + (size_t)(bn + r) * K + k0 + c * 8);
    }
}

__global__ __launch_bounds__(256, 2) void gemm_kernel(
    const fp16* __restrict__ Agh, const fp16* __restrict__ Bgh,
    const float* __restrict__ bias, const float* __restrict__ resid,
    float* __restrict__ C, fp16* __restrict__ Ch,
    int M, int N, int K, int epi)
{
    extern __shared__ __align__(16) fp16 sm[];
    const int tid  = threadIdx.x;
    const int lane = tid & 31;
    const int wid  = tid >> 5;
    const int warp_m = wid & 1;
    const int warp_n = wid >> 1;
    const int bm = blockIdx.y * 128;
    const int bn = blockIdx.x * 128;
    const uint32_t smB = smem_u32(sm);

    float acc[4][4][4];
    #pragma unroll
    for (int i = 0; i < 4; i++)
        #pragma unroll
        for (int j = 0; j < 4; j++)
            #pragma unroll
            for (int u = 0; u < 4; u++) acc[i][j][u] = 0.f;

    const int ntiles = K / BK;

    ld_stage(smB, Agh, Bgh, bm, bn, K, 0, tid);
    asm volatile("cp.async.commit_group;\n");
    if (ntiles > 1)
        ld_stage(smB + STAGE_B, Agh, Bgh, bm, bn, K, BK, tid);
    asm volatile("cp.async.commit_group;\n");

    const int lr = lane & 15, lc = lane >> 4;

    for (int kt = 0; kt < ntiles; kt++) {
        asm volatile("cp.async.wait_group 1;\n");
        __syncthreads();

        const int nx = kt + 2;
        if (nx < ntiles)
            ld_stage(smB + (nx % 3) * STAGE_B, Agh, Bgh, bm, bn, K, nx * BK, tid);
        asm volatile("cp.async.commit_group;\n");

        const uint32_t st = smB + (kt % 3) * STAGE_B;
        const uint32_t Ah = st;
        const uint32_t Bh = st + SUBB;

        #pragma unroll
        for (int kk = 0; kk < 4; kk++) {
            const int cch = kk * 2 + lc;
            uint32_t a[4][4], bh[4][2];
            #pragma unroll
            for (int i = 0; i < 4; i++) {
                const int r_ = warp_m*64 + i*16 + lr;
                ldmx4(a[i][0], a[i][1], a[i][2], a[i][3], Ah + swz(r_, cch));
            }
            #pragma unroll
            for (int j16 = 0; j16 < 2; j16++) {
                const int rb_ = warp_n*32 + j16*16 + lr;
                uint32_t r0, r1, r2, r3;
                ldmx4(r0, r1, r2, r3, Bh + swz(rb_, cch));
                bh[j16*2][0] = r0; bh[j16*2][1] = r2;
                bh[j16*2+1][0] = r1; bh[j16*2+1][1] = r3;
            }
            #pragma unroll
            for (int i = 0; i < 4; i++)
                #pragma unroll
                for (int j = 0; j < 4; j++)
                    mma16816(acc[i][j], a[i][0],a[i][1],a[i][2],a[i][3], bh[j][0],bh[j][1]);
        }
    }

    #pragma unroll
    for (int i = 0; i < 4; i++) {
        #pragma unroll
        for (int j = 0; j < 4; j++) {
            const int row0 = bm + warp_m*64 + i*16 + (lane >> 2);
            const int col  = bn + warp_n*32 + j*8 + 2*(lane & 3);
            const float2 bv = *(const float2*)(bias + col);
            #pragma unroll
            for (int half_ = 0; half_ < 2; half_++) {
                const int row = row0 + half_ * 8;
                float rx = acc[i][j][half_*2+0] + bv.x;
                float ry = acc[i][j][half_*2+1] + bv.y;
                if (epi == 1) {
                    rx = 0.5f * rx * (1.0f + erff(rx * 0.70710678118654752f));
                    ry = 0.5f * ry * (1.0f + erff(ry * 0.70710678118654752f));
                    *(uint32_t*)(Ch + (size_t)row*N + col) =
                        packh2(__float2half_rn(rx), __float2half_rn(ry));
                } else if (epi == 2) {
                    const float2 rv = *(const float2*)(resid + (size_t)row*N + col);
                    *(float2*)(C + (size_t)row*N + col) = make_float2(rx + rv.x, ry + rv.y);
                } else {
                    *(uint32_t*)(Ch + (size_t)row*N + col) =
                        packh2(__float2half_rn(rx), __float2half_rn(ry));
                }
            }
        }
    }
}

// ---------------- causal flash attention -------------------------------------
// 128-query blocks (8 warps x 16q), 64-k tiles, double-buffered K/V.
#define AT_LDT 72
#define AQ_BYTES (128*AT_LDT*2)
#define AKV_BYTES (64*AT_LDT*2)
#define ATT_SMEM (AQ_BYTES + 4*AKV_BYTES)

__global__ __launch_bounds__(256, 2) void attn_kernel(const fp16* __restrict__ QKVh)
{
    extern __shared__ __align__(16) fp16 asmem[];
    const uint32_t sQ  = smem_u32(asmem);
    const uint32_t sK0 = sQ + AQ_BYTES;
    const uint32_t sV0 = sQ + AQ_BYTES + 2*AKV_BYTES;

    const int h   = blockIdx.y;
    const int b   = blockIdx.z;
    const int tid = threadIdx.x;
    const int w    = tid >> 5;
    const int lane = tid & 31;
    const int lr = lane & 15, lc = lane >> 4;
    const int rr = lane >> 2, cq = lane & 3;

    #pragma unroll 1
    for (int ph_ = 0; ph_ < 2; ph_++) {
        const int qtp = ph_ ? (TT/128 - 1 - blockIdx.x) : blockIdx.x;
        const int qb  = qtp * 128;
        const int nkt = 2 * qtp + 2;

        #pragma unroll
        for (int c = tid; c < 1024; c += 256) {
            int row = c >> 3, seg = c & 7;
            size_t g = ((size_t)(b*TT + qb + row))*H3 + h*DD + seg*8;
            cp16(sQ + (uint32_t)(row*AT_LDT + seg*8)*2, QKVh + g);
        }
        #pragma unroll
        for (int c = tid; c < 512; c += 256) {
            int row = c >> 3, seg = c & 7;
            size_t gk = ((size_t)(b*TT + row))*H3 + HH + h*DD + seg*8;
            uint32_t s = (uint32_t)(row*AT_LDT + seg*8)*2;
            cp16(sK0 + s, QKVh + gk);
            cp16(sV0 + s, QKVh + gk + HH);
        }
        asm volatile("cp.async.commit_group;\n");

        float O[8][4];
        #pragma unroll
        for (int j = 0; j < 8; j++)
            #pragma unroll
            for (int u = 0; u < 4; u++) O[j][u] = 0.f;
        float m0 = -1e30f, m1 = -1e30f, l0 = 0.f, l1 = 0.f;

        for (int kt = 0; kt < nkt; kt++) {
            if (kt + 1 < nkt) {
                const uint32_t sKp = sK0 + ((kt + 1) & 1) * AKV_BYTES;
                const uint32_t sVp = sV0 + ((kt + 1) & 1) * AKV_BYTES;
                #pragma unroll
                for (int c = tid; c < 512; c += 256) {
                    int row = c >> 3, seg = c & 7;
                    size_t gk = ((size_t)(b*TT + (kt+1)*64 + row))*H3 + HH + h*DD + seg*8;
                    uint32_t s = (uint32_t)(row*AT_LDT + seg*8)*2;
                    cp16(sKp + s, QKVh + gk);
                    cp16(sVp + s, QKVh + gk + HH);
                }
            }
            asm volatile("cp.async.commit_group;\n");
            asm volatile("cp.async.wait_group 1;\n");
            __syncthreads();

            const bool active = (kt * 64 <= qb + w*16 + 15);
            if (active) {
                const uint32_t sK = sK0 + (kt & 1) * AKV_BYTES;
                const uint32_t sV = sV0 + (kt & 1) * AKV_BYTES;

                float S[8][4];
                #pragma unroll
                for (int j = 0; j < 8; j++)
                    #pragma unroll
                    for (int u = 0; u < 4; u++) S[j][u] = 0.f;

                #pragma unroll
                for (int ks = 0; ks < 4; ks++) {
                    const uint32_t coff = (uint32_t)(ks*16 + lc*8)*2;
                    uint32_t qh[4];
                    ldmx4(qh[0], qh[1], qh[2], qh[3],
                          sQ + (uint32_t)((w*16 + lr)*AT_LDT)*2 + coff);
                    #pragma unroll
                    for (int j16 = 0; j16 < 4; j16++) {
                        uint32_t rb = (uint32_t)((j16*16 + lr)*AT_LDT)*2 + coff;
                        uint32_t k0,k1,k2,k3;
                        ldmx4(k0,k1,k2,k3, sK + rb);
                        mma16816(S[j16*2],   qh[0],qh[1],qh[2],qh[3], k0,k2);
                        mma16816(S[j16*2+1], qh[0],qh[1],qh[2],qh[3], k1,k3);
                    }
                }

                #pragma unroll
                for (int j = 0; j < 8; j++)
                    #pragma unroll
                    for (int u = 0; u < 4; u++) S[j][u] *= 0.125f;

                if (kt*64 + 63 > qb + w*16) {
                    const int q0 = qb + w*16 + rr, q1 = q0 + 8;
                    #pragma unroll
                    for (int j = 0; j < 8; j++) {
                        const int c0 = kt*64 + 8*j + 2*cq, c1 = c0 + 1;
                        if (c0 > q0) S[j][0] = -1e30f;
                        if (c1 > q0) S[j][1] = -1e30f;
                        if (c0 > q1) S[j][2] = -1e30f;
                        if (c1 > q1) S[j][3] = -1e30f;
                    }
                }

                float t0 = -1e30f, t1 = -1e30f;
                #pragma unroll
                for (int j = 0; j < 8; j++) {
                    t0 = fmaxf(t0, fmaxf(S[j][0], S[j][1]));
                    t1 = fmaxf(t1, fmaxf(S[j][2], S[j][3]));
                }
                t0 = fmaxf(t0, __shfl_xor_sync(0xffffffffu, t0, 1));
                t0 = fmaxf(t0, __shfl_xor_sync(0xffffffffu, t0, 2));
                t1 = fmaxf(t1, __shfl_xor_sync(0xffffffffu, t1, 1));
                t1 = fmaxf(t1, __shfl_xor_sync(0xffffffffu, t1, 2));

                const float n0 = fmaxf(m0, t0), n1 = fmaxf(m1, t1);
                const float f0 = fexp(m0 - n0), f1 = fexp(m1 - n1);
                m0 = n0; m1 = n1;

                uint32_t ph2[8][2];
                float s0 = 0.f, s1 = 0.f;
                #pragma unroll
                for (int j = 0; j < 8; j++) {
                    float p0 = fexp(S[j][0] - n0), p1 = fexp(S[j][1] - n0);
                    float p2 = fexp(S[j][2] - n1), p3 = fexp(S[j][3] - n1);
                    s0 += p0 + p1; s1 += p2 + p3;
                    ph2[j][0] = packh2(__float2half_rn(p0), __float2half_rn(p1));
                    ph2[j][1] = packh2(__float2half_rn(p2), __float2half_rn(p3));
                }
                s0 += __shfl_xor_sync(0xffffffffu, s0, 1);
                s0 += __shfl_xor_sync(0xffffffffu, s0, 2);
                s1 += __shfl_xor_sync(0xffffffffu, s1, 1);
                s1 += __shfl_xor_sync(0xffffffffu, s1, 2);
                l0 = l0*f0 + s0; l1 = l1*f1 + s1;

                #pragma unroll
                for (int j = 0; j < 8; j++) {
                    O[j][0] *= f0; O[j][1] *= f0; O[j][2] *= f1; O[j][3] *= f1;
                }

                #pragma unroll
                for (int ks = 0; ks < 4; ks++) {
                    uint32_t a0 = ph2[2*ks][0], a1 = ph2[2*ks][1],
                             a2 = ph2[2*ks+1][0], a3 = ph2[2*ks+1][1];
                    #pragma unroll
                    for (int j16 = 0; j16 < 4; j16++) {
                        uint32_t rbv = (uint32_t)((ks*16 + lr)*AT_LDT + j16*16 + lc*8)*2;
                        uint32_t v0,v1,v2,v3;
                        ldmx4t(v0,v1,v2,v3, sV + rbv);
                        mma16816(O[2*j16],   a0,a1,a2,a3, v0,v1);
                        mma16816(O[2*j16+1], a0,a1,a2,a3, v2,v3);
                    }
                }
            }
            __syncthreads();
        }

        const float inv0 = 1.f / l0, inv1 = 1.f / l1;
        const size_t row0 = (size_t)(b*TT + qb + w*16 + rr);
        const size_t row1 = row0 + 8;
        #pragma unroll
        for (int j = 0; j < 8; j++) {
            const int col = h*DD + 8*j + 2*cq;
            *(uint32_t*)(g_oh + row0*HH + col) =
                packh2(__float2half_rn(O[j][0]*inv0), __float2half_rn(O[j][1]*inv0));
            *(uint32_t*)(g_oh + row1*HH + col) =
                packh2(__float2half_rn(O[j][2]*inv1), __float2half_rn(O[j][3]*inv1));
        }
        __syncthreads();
    }
}

// ---------------- LayerNorm (warp-shuffle reduction) -------------------------
__global__ __launch_bounds__(256) void ln_kernel(
    const float* __restrict__ in, const float* __restrict__ gamma,
    const float* __restrict__ beta, float* __restrict__ out,
    fp16* __restrict__ outh)
{
    __shared__ float ws[8], ws2[8];
    const int row = blockIdx.x;
    const int tid = threadIdx.x;
    const int lane = tid & 31, wid = tid >> 5;
    const float* p = in + (size_t)row * HH;

    float4 v = *(const float4*)(p + tid * 4);
    float s = v.x + v.y + v.z + v.w;
    float q = v.x*v.x + v.y*v.y + v.z*v.z + v.w*v.w;
    #pragma unroll
    for (int off = 16; off > 0; off >>= 1) {
        s += __shfl_xor_sync(0xffffffffu, s, off);
        q += __shfl_xor_sync(0xffffffffu, q, off);
    }
    if (lane == 0) { ws[wid] = s; ws2[wid] = q; }
    __syncthreads();
    float ts = 0.f, tq = 0.f;
    #pragma unroll
    for (int u = 0; u < 8; u++) { ts += ws[u]; tq += ws2[u]; }
    const float mean = ts * (1.0f / HH);
    const float var  = tq * (1.0f / HH) - mean * mean;
    const float rstd = rsqrtf(var + 1e-5f);

    float dx = v.x-mean, dy = v.y-mean, dz = v.z-mean, dw = v.w-mean;
    float4 g  = *(const float4*)(gamma + tid * 4);
    float4 be = *(const float4*)(beta + tid * 4);
    float4 rr;
    rr.x = dx*rstd*g.x + be.x;
    rr.y = dy*rstd*g.y + be.y;
    rr.z = dz*rstd*g.z + be.z;
    rr.w = dw*rstd*g.w + be.w;
    *(float4*)(out + (size_t)row*HH + tid*4) = rr;
    *(uint2*)(outh + (size_t)row*HH + tid*4) =
        make_uint2(packh2(__float2half_rn(rr.x), __float2half_rn(rr.y)),
                   packh2(__float2half_rn(rr.z), __float2half_rn(rr.w)));
}

// ---------------- launcher -------------------------------------------------
extern "C" void kernel_launch(void* const* d_in, const int* in_sizes, int n_in,
                              void* d_out, int out_size)
{
    const float* Wq  = (const float*)d_in[1];
    const float* bq  = (const float*)d_in[2];
    const float* Wk  = (const float*)d_in[3];
    const float* bk  = (const float*)d_in[4];
    const float* Wv  = (const float*)d_in[5];
    const float* bv  = (const float*)d_in[6];
    const float* Wp  = (const float*)d_in[7];
    const float* bp  = (const float*)d_in[8];
    const float* W1  = (const float*)d_in[9];
    const float* b1  = (const float*)d_in[10];
    const float* W2  = (const float*)d_in[11];
    const float* b2  = (const float*)d_in[12];
    const float* g1w = (const float*)d_in[13];
    const float* be1 = (const float*)d_in[14];
    const float* g2w = (const float*)d_in[15];
    const float* be2 = (const float*)d_in[16];

    cudaFuncSetAttribute(gemm_kernel, cudaFuncAttributeMaxDynamicSharedMemorySize, GEMM_SMEM);
    cudaFuncSetAttribute(attn_kernel, cudaFuncAttributeMaxDynamicSharedMemorySize, ATT_SMEM);

    float *gx, *gt, *gbqkv;
    fp16 *gxh, *gqkvh, *goh, *ghh;
    fp16 *wqh, *wph, *w1h, *w2h;
    cudaGetSymbolAddress((void**)&gx,    g_x);
    cudaGetSymbolAddress((void**)&gxh,   g_xh);
    cudaGetSymbolAddress((void**)&gqkvh, g_qkvh);
    cudaGetSymbolAddress((void**)&goh,   g_oh);
    cudaGetSymbolAddress((void**)&gt,    g_t);
    cudaGetSymbolAddress((void**)&ghh,   g_hh);
    cudaGetSymbolAddress((void**)&wqh,   w_qkv_h);
    cudaGetSymbolAddress((void**)&wph,   w_p_h);
    cudaGetSymbolAddress((void**)&w1h,   w_1_h);
    cudaGetSymbolAddress((void**)&w2h,   w_2_h);
    cudaGetSymbolAddress((void**)&gbqkv, g_bqkv);

    wsplit_all<<<TOT_TILES, 256>>>(Wq, Wk, Wv, Wp, W1, W2);
    prep_kernel<<<(MM*HH/4 + 255)/256, 256>>>((const float*)d_in[0], bq, bk, bv);

    const dim3 gridQKV(H3/128, MM/128);   // (24, 32)
    const dim3 gridH(HH/128, MM/128);     // (8, 32)
    const dim3 gridF(FFF/128, MM/128);    // (32, 32)
    const dim3 gridA(TT/256, NHH, BB);    // paired 128q-tiles: (8, 16, 2)

    for (int l = 0; l < LL; l++) {
        const size_t bo = (size_t)l * HH;

        gemm_kernel<<<gridQKV, 256, GEMM_SMEM>>>(
            gxh, wqh + (size_t)l*H3*HH,
            gbqkv + (size_t)l*H3, nullptr, nullptr, gqkvh,
            MM, H3, HH, 3);

        attn_kernel<<<gridA, 256, ATT_SMEM>>>(gqkvh);

        gemm_kernel<<<gridH, 256, GEMM_SMEM>>>(
            goh, wph + (size_t)l*HH*HH,
            bp + bo, gx, gt, nullptr, MM, HH, HH, 2);
        ln_kernel<<<MM, 256>>>(gt, g1w + bo, be1 + bo, gx, gxh);

        gemm_kernel<<<gridF, 256, GEMM_SMEM>>>(
            gxh, w1h + (size_t)l*FFF*HH,
            b1 + (size_t)l*FFF, nullptr, nullptr, ghh, MM, FFF, HH, 1);
        gemm_kernel<<<gridH, 256, GEMM_SMEM>>>(
            ghh, w2h + (size_t)l*HH*FFF,
            b2 + bo, gx, gt, nullptr, MM, HH, FFF, 2);
        ln_kernel<<<MM, 256>>>(gt, g2w + bo, be2 + bo, gx, gxh);
    }

    cudaMemcpyAsync(d_out, gx, (size_t)MM*HH*sizeof(float),
                    cudaMemcpyDeviceToDevice, 0);
}

// round 14
// speedup vs baseline: 1.5110x; 1.0103x over previous
#include <cuda_runtime.h>
#include <cuda_fp16.h>
#include <math.h>
#include <stdint.h>

#define BB 2
#define TT 2048
#define HH 1024
#define NHH 16
#define DD 64
#define FFF 4096
#define LL 6
#define MM (BB*TT)
#define H3 (3*HH)

typedef __half fp16;

// ---------------- device-global scratch ------------------------------------
__device__ float g_x [MM*HH];
__device__ fp16  g_xh[MM*HH];
__device__ fp16  g_qkvh[MM*H3];
__device__ fp16  g_oh[MM*HH];
__device__ float g_t [MM*HH];
__device__ fp16  g_hh[MM*FFF];
__device__ fp16  w_qkv_h[LL*H3*HH];
__device__ fp16  w_p_h  [LL*HH*HH];
__device__ fp16  w_1_h  [LL*FFF*HH];
__device__ fp16  w_2_h  [LL*HH*FFF];
__device__ float g_bqkv[LL*H3];

// ---------------- helpers ---------------------------------------------------
__device__ __forceinline__ uint32_t pk2(float a, float b) {
    __half2 h = __floats2half2_rn(a, b);          // single F2FP.PACK_AB
    return *(uint32_t*)&h;
}
__device__ __forceinline__ uint32_t smem_u32(const void* p) {
    return (uint32_t)__cvta_generic_to_shared(p);
}
__device__ __forceinline__ void cp16(uint32_t s, const void* g) {
    asm volatile("cp.async.cg.shared.global [%0],[%1],16;\n" :: "r"(s), "l"(g));
}
__device__ __forceinline__ void ldmx4(uint32_t& r0, uint32_t& r1, uint32_t& r2,
                                      uint32_t& r3, uint32_t addr) {
    asm volatile("ldmatrix.sync.aligned.m8n8.x4.shared.b16 {%0,%1,%2,%3},[%4];\n"
                 : "=r"(r0), "=r"(r1), "=r"(r2), "=r"(r3) : "r"(addr));
}
__device__ __forceinline__ void ldmx4t(uint32_t& r0, uint32_t& r1, uint32_t& r2,
                                       uint32_t& r3, uint32_t addr) {
    asm volatile("ldmatrix.sync.aligned.m8n8.x4.trans.shared.b16 {%0,%1,%2,%3},[%4];\n"
                 : "=r"(r0), "=r"(r1), "=r"(r2), "=r"(r3) : "r"(addr));
}
__device__ __forceinline__ void mma16816(float c[4], uint32_t a0, uint32_t a1,
                                         uint32_t a2, uint32_t a3,
                                         uint32_t b0, uint32_t b1) {
    asm volatile(
        "mma.sync.aligned.m16n8k16.row.col.f32.f16.f16.f32 "
        "{%0,%1,%2,%3}, {%4,%5,%6,%7}, {%8,%9}, {%0,%1,%2,%3};"
        : "+f"(c[0]), "+f"(c[1]), "+f"(c[2]), "+f"(c[3])
        : "r"(a0), "r"(a1), "r"(a2), "r"(a3), "r"(b0), "r"(b1));
}

// FMA-pipe e^x, degree-3 (result feeds fp16 P; rel err ~2e-4 < fp16 ulp).
__device__ __forceinline__ float fexp(float x) {
    x = fmaxf(x, -87.0f);
    const float L2E = 1.4426950408889634f;
    float t = fmaf(x, L2E, 12582912.0f);
    float i = t - 12582912.0f;
    float f = fmaf(x, L2E, -i);
    float p =            5.550357e-2f;
    p = fmaf(p, f, 2.402291e-1f);
    p = fmaf(p, f, 6.931406e-1f);
    p = fmaf(p, f, 1.0f);
    int eb = (__float_as_int(t) - 0x4B400000 + 127) << 23;
    return __int_as_float(eb) * p;
}

// ---------------- single fused weight transpose (fp16) ----------------------
#define QKV_TILES 18432
#define WP_END    24576
#define W1_END    49152
#define TOT_TILES 73728

__global__ __launch_bounds__(256) void wsplit_all(
    const float* __restrict__ Wq, const float* __restrict__ Wk,
    const float* __restrict__ Wv, const float* __restrict__ Wp,
    const float* __restrict__ W1, const float* __restrict__ W2)
{
    __shared__ float tbuf[32][33];
    const int t = blockIdx.x;
    const float* src; fp16 *dh;
    int K, N, n0, k0;
    if (t < QKV_TILES) {
        int z = t >> 10, r = t & 1023;
        int l = z / 3, wch = z % 3;
        src = (wch == 0 ? Wq : wch == 1 ? Wk : Wv) + (size_t)l * HH * HH;
        dh = w_qkv_h + (size_t)l * H3 * HH + (size_t)wch * HH * HH;
        K = HH; N = HH; n0 = (r & 31) * 32; k0 = (r >> 5) * 32;
    } else if (t < WP_END) {
        int t2 = t - QKV_TILES; int l = t2 >> 10, r = t2 & 1023;
        src = Wp + (size_t)l * HH * HH;
        dh = w_p_h + (size_t)l * HH * HH;
        K = HH; N = HH; n0 = (r & 31) * 32; k0 = (r >> 5) * 32;
    } else if (t < W1_END) {
        int t3 = t - WP_END; int l = t3 >> 12, r = t3 & 4095;
        src = W1 + (size_t)l * HH * FFF;
        dh = w_1_h + (size_t)l * FFF * HH;
        K = HH; N = FFF; n0 = (r & 127) * 32; k0 = (r >> 7) * 32;
    } else {
        int t4 = t - W1_END; int l = t4 >> 12, r = t4 & 4095;
        src = W2 + (size_t)l * FFF * HH;
        dh = w_2_h + (size_t)l * HH * FFF;
        K = FFF; N = HH; n0 = (r & 31) * 32; k0 = (r >> 5) * 32;
    }

    const int tx = threadIdx.x & 31, ty = threadIdx.x >> 5;
    #pragma unroll
    for (int u = 0; u < 4; u++)
        tbuf[ty + u * 8][tx] = src[(size_t)(k0 + ty + u * 8) * N + n0 + tx];
    __syncthreads();
    #pragma unroll
    for (int u = 0; u < 4; u++) {
        size_t o = (size_t)(n0 + ty + u * 8) * K + k0 + tx;
        dh[o] = __float2half_rn(tbuf[tx][ty + u * 8]);
    }
}

__global__ void prep_kernel(const float* __restrict__ in,
                            const float* bq, const float* bk, const float* bv)
{
    int id = blockIdx.x * blockDim.x + threadIdx.x;
    if (id < LL * H3) {
        int l = id / H3, c = id % H3;
        g_bqkv[id] = (c < HH) ? bq[l*HH + c]
                   : (c < 2*HH) ? bk[l*HH + c - HH] : bv[l*HH + c - 2*HH];
    }
    if (id < MM*HH/4) {
        float4 v = *(const float4*)(in + (size_t)id * 4);
        *(float4*)(g_x + (size_t)id * 4) = v;
        *(uint2*)(g_xh + (size_t)id * 4) =
            make_uint2(pk2(v.x, v.y), pk2(v.z, v.w));
    }
}

// ---------------- GEMM (fp16 1-term, BK=64, 256 thr, warp tile 64x32) --------
// epi: 1 bias+gelu->hi, 2 bias+resid->f32, 3 bias->hi (QKV: Q third scaled /8)
#define BK 64
#define SUBB 16384
#define STAGE_B (2*SUBB)           // Ah Bh = 32 KB
#define GEMM_SMEM (3*STAGE_B)      // 96 KB

__device__ __forceinline__ uint32_t swz(int r, int c) {   // c = 16B chunk 0..7
    return (uint32_t)(r * 128 + ((c ^ (r & 7)) << 4));
}

__device__ __forceinline__ void ld_stage(
    uint32_t st, const fp16* Agh, const fp16* Bgh,
    int bm, int bn, int K, int k0, int tid)
{
    #pragma unroll
    for (int u = tid; u < 1024; u += 256) {
        const int r = u >> 3, c = u & 7;
        const uint32_t sw = swz(r, c);
        cp16(st + sw,         Agh + (size_t)(bm + r) * K + k0 + c * 8);
        cp16(st + SUBB + sw,  Bgh + (size_t)(bn + r) * K + k0 + c * 8);
    }
}

__global__ __launch_bounds__(256, 2) void gemm_kernel(
    const fp16* __restrict__ Agh, const fp16* __restrict__ Bgh,
    const float* __restrict__ bias, const float* __restrict__ resid,
    float* __restrict__ C, fp16* __restrict__ Ch,
    int M, int N, int K, int epi)
{
    extern __shared__ __align__(16) fp16 sm[];
    const int tid  = threadIdx.x;
    const int lane = tid & 31;
    const int wid  = tid >> 5;
    const int warp_m = wid & 1;
    const int warp_n = wid >> 1;
    const int bm = blockIdx.y * 128;
    const int bn = blockIdx.x * 128;
    const uint32_t smB = smem_u32(sm);

    float acc[4][4][4];
    #pragma unroll
    for (int i = 0; i < 4; i++)
        #pragma unroll
        for (int j = 0; j < 4; j++)
            #pragma unroll
            for (int u = 0; u < 4; u++) acc[i][j][u] = 0.f;

    const int ntiles = K / BK;

    ld_stage(smB, Agh, Bgh, bm, bn, K, 0, tid);
    asm volatile("cp.async.commit_group;\n");
    if (ntiles > 1)
        ld_stage(smB + STAGE_B, Agh, Bgh, bm, bn, K, BK, tid);
    asm volatile("cp.async.commit_group;\n");

    const int lr = lane & 15, lc = lane >> 4;

    for (int kt = 0; kt < ntiles; kt++) {
        asm volatile("cp.async.wait_group 1;\n");
        __syncthreads();

        const int nx = kt + 2;
        if (nx < ntiles)
            ld_stage(smB + (nx % 3) * STAGE_B, Agh, Bgh, bm, bn, K, nx * BK, tid);
        asm volatile("cp.async.commit_group;\n");

        const uint32_t st = smB + (kt % 3) * STAGE_B;
        const uint32_t Ah = st;
        const uint32_t Bh = st + SUBB;

        #pragma unroll
        for (int kk = 0; kk < 4; kk++) {
            const int cch = kk * 2 + lc;
            uint32_t a[4][4], bh[4][2];
            #pragma unroll
            for (int i = 0; i < 4; i++) {
                const int r_ = warp_m*64 + i*16 + lr;
                ldmx4(a[i][0], a[i][1], a[i][2], a[i][3], Ah + swz(r_, cch));
            }
            #pragma unroll
            for (int j16 = 0; j16 < 2; j16++) {
                const int rb_ = warp_n*32 + j16*16 + lr;
                uint32_t r0, r1, r2, r3;
                ldmx4(r0, r1, r2, r3, Bh + swz(rb_, cch));
                bh[j16*2][0] = r0; bh[j16*2][1] = r2;
                bh[j16*2+1][0] = r1; bh[j16*2+1][1] = r3;
            }
            #pragma unroll
            for (int i = 0; i < 4; i++)
                #pragma unroll
                for (int j = 0; j < 4; j++)
                    mma16816(acc[i][j], a[i][0],a[i][1],a[i][2],a[i][3], bh[j][0],bh[j][1]);
        }
    }

    #pragma unroll
    for (int i = 0; i < 4; i++) {
        #pragma unroll
        for (int j = 0; j < 4; j++) {
            const int row0 = bm + warp_m*64 + i*16 + (lane >> 2);
            const int col  = bn + warp_n*32 + j*8 + 2*(lane & 3);
            const float2 bv = *(const float2*)(bias + col);
            #pragma unroll
            for (int half_ = 0; half_ < 2; half_++) {
                const int row = row0 + half_ * 8;
                float rx = acc[i][j][half_*2+0] + bv.x;
                float ry = acc[i][j][half_*2+1] + bv.y;
                if (epi == 1) {
                    rx = 0.5f * rx * (1.0f + erff(rx * 0.70710678118654752f));
                    ry = 0.5f * ry * (1.0f + erff(ry * 0.70710678118654752f));
                    *(uint32_t*)(Ch + (size_t)row*N + col) = pk2(rx, ry);
                } else if (epi == 2) {
                    const float2 rv = *(const float2*)(resid + (size_t)row*N + col);
                    *(float2*)(C + (size_t)row*N + col) = make_float2(rx + rv.x, ry + rv.y);
                } else {
                    // epi==3 (QKV): pre-scale the Q third by 1/sqrt(D)=0.125
                    if (col < HH) { rx *= 0.125f; ry *= 0.125f; }
                    *(uint32_t*)(Ch + (size_t)row*N + col) = pk2(rx, ry);
                }
            }
        }
    }
}

// ---------------- causal flash attention -------------------------------------
// 128-query blocks (8 warps x 16q), 64-k tiles, double-buffered K/V.
// Q is pre-scaled by 0.125 at the QKV epilogue (no S scaling here).
#define AT_LDT 72
#define AQ_BYTES (128*AT_LDT*2)
#define AKV_BYTES (64*AT_LDT*2)
#define ATT_SMEM (AQ_BYTES + 4*AKV_BYTES)

__global__ __launch_bounds__(256, 2) void attn_kernel(const fp16* __restrict__ QKVh)
{
    extern __shared__ __align__(16) fp16 asmem[];
    const uint32_t sQ  = smem_u32(asmem);
    const uint32_t sK0 = sQ + AQ_BYTES;
    const uint32_t sV0 = sQ + AQ_BYTES + 2*AKV_BYTES;

    const int h   = blockIdx.y;
    const int b   = blockIdx.z;
    const int tid = threadIdx.x;
    const int w    = tid >> 5;
    const int lane = tid & 31;
    const int lr = lane & 15, lc = lane >> 4;
    const int rr = lane >> 2, cq = lane & 3;

    #pragma unroll 1
    for (int ph_ = 0; ph_ < 2; ph_++) {
        const int qtp = ph_ ? (TT/128 - 1 - blockIdx.x) : blockIdx.x;
        const int qb  = qtp * 128;
        const int nkt = 2 * qtp + 2;

        #pragma unroll
        for (int c = tid; c < 1024; c += 256) {
            int row = c >> 3, seg = c & 7;
            size_t g = ((size_t)(b*TT + qb + row))*H3 + h*DD + seg*8;
            cp16(sQ + (uint32_t)(row*AT_LDT + seg*8)*2, QKVh + g);
        }
        #pragma unroll
        for (int c = tid; c < 512; c += 256) {
            int row = c >> 3, seg = c & 7;
            size_t gk = ((size_t)(b*TT + row))*H3 + HH + h*DD + seg*8;
            uint32_t s = (uint32_t)(row*AT_LDT + seg*8)*2;
            cp16(sK0 + s, QKVh + gk);
            cp16(sV0 + s, QKVh + gk + HH);
        }
        asm volatile("cp.async.commit_group;\n");

        float O[8][4];
        #pragma unroll
        for (int j = 0; j < 8; j++)
            #pragma unroll
            for (int u = 0; u < 4; u++) O[j][u] = 0.f;
        float m0 = -1e30f, m1 = -1e30f, l0 = 0.f, l1 = 0.f;

        for (int kt = 0; kt < nkt; kt++) {
            if (kt + 1 < nkt) {
                const uint32_t sKp = sK0 + ((kt + 1) & 1) * AKV_BYTES;
                const uint32_t sVp = sV0 + ((kt + 1) & 1) * AKV_BYTES;
                #pragma unroll
                for (int c = tid; c < 512; c += 256) {
                    int row = c >> 3, seg = c & 7;
                    size_t gk = ((size_t)(b*TT + (kt+1)*64 + row))*H3 + HH + h*DD + seg*8;
                    uint32_t s = (uint32_t)(row*AT_LDT + seg*8)*2;
                    cp16(sKp + s, QKVh + gk);
                    cp16(sVp + s, QKVh + gk + HH);
                }
            }
            asm volatile("cp.async.commit_group;\n");
            asm volatile("cp.async.wait_group 1;\n");
            __syncthreads();

            const bool active = (kt * 64 <= qb + w*16 + 15);
            if (active) {
                const uint32_t sK = sK0 + (kt & 1) * AKV_BYTES;
                const uint32_t sV = sV0 + (kt & 1) * AKV_BYTES;

                float S[8][4];
                #pragma unroll
                for (int j = 0; j < 8; j++)
                    #pragma unroll
                    for (int u = 0; u < 4; u++) S[j][u] = 0.f;

                #pragma unroll
                for (int ks = 0; ks < 4; ks++) {
                    const uint32_t coff = (uint32_t)(ks*16 + lc*8)*2;
                    uint32_t qh[4];
                    ldmx4(qh[0], qh[1], qh[2], qh[3],
                          sQ + (uint32_t)((w*16 + lr)*AT_LDT)*2 + coff);
                    #pragma unroll
                    for (int j16 = 0; j16 < 4; j16++) {
                        uint32_t rb = (uint32_t)((j16*16 + lr)*AT_LDT)*2 + coff;
                        uint32_t k0,k1,k2,k3;
                        ldmx4(k0,k1,k2,k3, sK + rb);
                        mma16816(S[j16*2],   qh[0],qh[1],qh[2],qh[3], k0,k2);
                        mma16816(S[j16*2+1], qh[0],qh[1],qh[2],qh[3], k1,k3);
                    }
                }

                if (kt*64 + 63 > qb + w*16) {
                    const int q0 = qb + w*16 + rr, q1 = q0 + 8;
                    #pragma unroll
                    for (int j = 0; j < 8; j++) {
                        const int c0 = kt*64 + 8*j + 2*cq, c1 = c0 + 1;
                        if (c0 > q0) S[j][0] = -1e30f;
                        if (c1 > q0) S[j][1] = -1e30f;
                        if (c0 > q1) S[j][2] = -1e30f;
                        if (c1 > q1) S[j][3] = -1e30f;
                    }
                }

                float t0 = -1e30f, t1 = -1e30f;
                #pragma unroll
                for (int j = 0; j < 8; j++) {
                    t0 = fmaxf(t0, fmaxf(S[j][0], S[j][1]));
                    t1 = fmaxf(t1, fmaxf(S[j][2], S[j][3]));
                }
                t0 = fmaxf(t0, __shfl_xor_sync(0xffffffffu, t0, 1));
                t0 = fmaxf(t0, __shfl_xor_sync(0xffffffffu, t0, 2));
                t1 = fmaxf(t1, __shfl_xor_sync(0xffffffffu, t1, 1));
                t1 = fmaxf(t1, __shfl_xor_sync(0xffffffffu, t1, 2));

                const float n0 = fmaxf(m0, t0), n1 = fmaxf(m1, t1);
                const float f0 = fexp(m0 - n0), f1 = fexp(m1 - n1);
                m0 = n0; m1 = n1;

                uint32_t ph2[8][2];
                float s0 = 0.f, s1 = 0.f;
                #pragma unroll
                for (int j = 0; j < 8; j++) {
                    float p0 = fexp(S[j][0] - n0), p1 = fexp(S[j][1] - n0);
                    float p2 = fexp(S[j][2] - n1), p3 = fexp(S[j][3] - n1);
                    s0 += p0 + p1; s1 += p2 + p3;
                    ph2[j][0] = pk2(p0, p1);
                    ph2[j][1] = pk2(p2, p3);
                }
                s0 += __shfl_xor_sync(0xffffffffu, s0, 1);
                s0 += __shfl_xor_sync(0xffffffffu, s0, 2);
                s1 += __shfl_xor_sync(0xffffffffu, s1, 1);
                s1 += __shfl_xor_sync(0xffffffffu, s1, 2);
                l0 = l0*f0 + s0; l1 = l1*f1 + s1;

                #pragma unroll
                for (int j = 0; j < 8; j++) {
                    O[j][0] *= f0; O[j][1] *= f0; O[j][2] *= f1; O[j][3] *= f1;
                }

                #pragma unroll
                for (int ks = 0; ks < 4; ks++) {
                    uint32_t a0 = ph2[2*ks][0], a1 = ph2[2*ks][1],
                             a2 = ph2[2*ks+1][0], a3 = ph2[2*ks+1][1];
                    #pragma unroll
                    for (int j16 = 0; j16 < 4; j16++) {
                        uint32_t rbv = (uint32_t)((ks*16 + lr)*AT_LDT + j16*16 + lc*8)*2;
                        uint32_t v0,v1,v2,v3;
                        ldmx4t(v0,v1,v2,v3, sV + rbv);
                        mma16816(O[2*j16],   a0,a1,a2,a3, v0,v1);
                        mma16816(O[2*j16+1], a0,a1,a2,a3, v2,v3);
                    }
                }
            }
            __syncthreads();
        }

        const float inv0 = 1.f / l0, inv1 = 1.f / l1;
        const size_t row0 = (size_t)(b*TT + qb + w*16 + rr);
        const size_t row1 = row0 + 8;
        #pragma unroll
        for (int j = 0; j < 8; j++) {
            const int col = h*DD + 8*j + 2*cq;
            *(uint32_t*)(g_oh + row0*HH + col) = pk2(O[j][0]*inv0, O[j][1]*inv0);
            *(uint32_t*)(g_oh + row1*HH + col) = pk2(O[j][2]*inv1, O[j][3]*inv1);
        }
        __syncthreads();
    }
}

// ---------------- LayerNorm (warp-shuffle reduction) -------------------------
__global__ __launch_bounds__(256) void ln_kernel(
    const float* __restrict__ in, const float* __restrict__ gamma,
    const float* __restrict__ beta, float* __restrict__ out,
    fp16* __restrict__ outh)
{
    __shared__ float ws[8], ws2[8];
    const int row = blockIdx.x;
    const int tid = threadIdx.x;
    const int lane = tid & 31, wid = tid >> 5;
    const float* p = in + (size_t)row * HH;

    float4 v = *(const float4*)(p + tid * 4);
    float s = v.x + v.y + v.z + v.w;
    float q = v.x*v.x + v.y*v.y + v.z*v.z + v.w*v.w;
    #pragma unroll
    for (int off = 16; off > 0; off >>= 1) {
        s += __shfl_xor_sync(0xffffffffu, s, off);
        q += __shfl_xor_sync(0xffffffffu, q, off);
    }
    if (lane == 0) { ws[wid] = s; ws2[wid] = q; }
    __syncthreads();
    float ts = 0.f, tq = 0.f;
    #pragma unroll
    for (int u = 0; u < 8; u++) { ts += ws[u]; tq += ws2[u]; }
    const float mean = ts * (1.0f / HH);
    const float var  = tq * (1.0f / HH) - mean * mean;
    const float rstd = rsqrtf(var + 1e-5f);

    float dx = v.x-mean, dy = v.y-mean, dz = v.z-mean, dw = v.w-mean;
    float4 g  = *(const float4*)(gamma + tid * 4);
    float4 be = *(const float4*)(beta + tid * 4);
    float4 rr;
    rr.x = dx*rstd*g.x + be.x;
    rr.y = dy*rstd*g.y + be.y;
    rr.z = dz*rstd*g.z + be.z;
    rr.w = dw*rstd*g.w + be.w;
    *(float4*)(out + (size_t)row*HH + tid*4) = rr;
    *(uint2*)(outh + (size_t)row*HH + tid*4) =
        make_uint2(pk2(rr.x, rr.y), pk2(rr.z, rr.w));
}

// ---------------- launcher -------------------------------------------------
extern "C" void kernel_launch(void* const* d_in, const int* in_sizes, int n_in,
                              void* d_out, int out_size)
{
    const float* Wq  = (const float*)d_in[1];
    const float* bq  = (const float*)d_in[2];
    const float* Wk  = (const float*)d_in[3];
    const float* bk  = (const float*)d_in[4];
    const float* Wv  = (const float*)d_in[5];
    const float* bv  = (const float*)d_in[6];
    const float* Wp  = (const float*)d_in[7];
    const float* bp  = (const float*)d_in[8];
    const float* W1  = (const float*)d_in[9];
    const float* b1  = (const float*)d_in[10];
    const float* W2  = (const float*)d_in[11];
    const float* b2  = (const float*)d_in[12];
    const float* g1w = (const float*)d_in[13];
    const float* be1 = (const float*)d_in[14];
    const float* g2w = (const float*)d_in[15];
    const float* be2 = (const float*)d_in[16];

    cudaFuncSetAttribute(gemm_kernel, cudaFuncAttributeMaxDynamicSharedMemorySize, GEMM_SMEM);
    cudaFuncSetAttribute(attn_kernel, cudaFuncAttributeMaxDynamicSharedMemorySize, ATT_SMEM);

    float *gx, *gt, *gbqkv;
    fp16 *gxh, *gqkvh, *goh, *ghh;
    fp16 *wqh, *wph, *w1h, *w2h;
    cudaGetSymbolAddress((void**)&gx,    g_x);
    cudaGetSymbolAddress((void**)&gxh,   g_xh);
    cudaGetSymbolAddress((void**)&gqkvh, g_qkvh);
    cudaGetSymbolAddress((void**)&goh,   g_oh);
    cudaGetSymbolAddress((void**)&gt,    g_t);
    cudaGetSymbolAddress((void**)&ghh,   g_hh);
    cudaGetSymbolAddress((void**)&wqh,   w_qkv_h);
    cudaGetSymbolAddress((void**)&wph,   w_p_h);
    cudaGetSymbolAddress((void**)&w1h,   w_1_h);
    cudaGetSymbolAddress((void**)&w2h,   w_2_h);
    cudaGetSymbolAddress((void**)&gbqkv, g_bqkv);

    wsplit_all<<<TOT_TILES, 256>>>(Wq, Wk, Wv, Wp, W1, W2);
    prep_kernel<<<(MM*HH/4 + 255)/256, 256>>>((const float*)d_in[0], bq, bk, bv);

    const dim3 gridQKV(H3/128, MM/128);   // (24, 32)
    const dim3 gridH(HH/128, MM/128);     // (8, 32)
    const dim3 gridF(FFF/128, MM/128);    // (32, 32)
    const dim3 gridA(TT/256, NHH, BB);    // paired 128q-tiles: (8, 16, 2)

    for (int l = 0; l < LL; l++) {
        const size_t bo = (size_t)l * HH;

        gemm_kernel<<<gridQKV, 256, GEMM_SMEM>>>(
            gxh, wqh + (size_t)l*H3*HH,
            gbqkv + (size_t)l*H3, nullptr, nullptr, gqkvh,
            MM, H3, HH, 3);

        attn_kernel<<<gridA, 256, ATT_SMEM>>>(gqkvh);

        gemm_kernel<<<gridH, 256, GEMM_SMEM>>>(
            goh, wph + (size_t)l*HH*HH,
            bp + bo, gx, gt, nullptr, MM, HH, HH, 2);
        ln_kernel<<<MM, 256>>>(gt, g1w + bo, be1 + bo, gx, gxh);

        gemm_kernel<<<gridF, 256, GEMM_SMEM>>>(
            gxh, w1h + (size_t)l*FFF*HH,
            b1 + (size_t)l*FFF, nullptr, nullptr, ghh, MM, FFF, HH, 1);
        gemm_kernel<<<gridH, 256, GEMM_SMEM>>>(
            ghh, w2h + (size_t)l*HH*FFF,
            b2 + bo, gx, gt, nullptr, MM, HH, FFF, 2);
        ln_kernel<<<MM, 256>>>(gt, g2w + bo, be2 + bo, gx, gxh);
    }

    cudaMemcpyAsync(d_out, gx, (size_t)MM*HH*sizeof(float),
                    cudaMemcpyDeviceToDevice, 0);
}

// round 15
// speedup vs baseline: 1.5140x; 1.0020x over previous
#include <cuda_runtime.h>
#include <cuda_fp16.h>
#include <math.h>
#include <stdint.h>

#define BB 2
#define TT 2048
#define HH 1024
#define NHH 16
#define DD 64
#define FFF 4096
#define LL 6
#define MM (BB*TT)
#define H3 (3*HH)

typedef __half fp16;

// ---------------- device-global scratch ------------------------------------
__device__ float g_x [MM*HH];
__device__ fp16  g_xh[MM*HH];
__device__ fp16  g_qkvh[MM*H3];
__device__ fp16  g_oh[MM*HH];
__device__ float g_t [MM*HH];
__device__ fp16  g_hh[MM*FFF];
__device__ fp16  w_qkv_h[LL*H3*HH];
__device__ fp16  w_p_h  [LL*HH*HH];
__device__ fp16  w_1_h  [LL*FFF*HH];
__device__ fp16  w_2_h  [LL*HH*FFF];
__device__ float g_bqkv[LL*H3];

// ---------------- helpers ---------------------------------------------------
__device__ __forceinline__ uint32_t pk2(float a, float b) {
    __half2 h = __floats2half2_rn(a, b);
    return *(uint32_t*)&h;
}
__device__ __forceinline__ uint32_t smem_u32(const void* p) {
    return (uint32_t)__cvta_generic_to_shared(p);
}
__device__ __forceinline__ void cp16(uint32_t s, const void* g) {
    asm volatile("cp.async.cg.shared.global [%0],[%1],16;\n" :: "r"(s), "l"(g));
}
__device__ __forceinline__ void ldmx4(uint32_t& r0, uint32_t& r1, uint32_t& r2,
                                      uint32_t& r3, uint32_t addr) {
    asm volatile("ldmatrix.sync.aligned.m8n8.x4.shared.b16 {%0,%1,%2,%3},[%4];\n"
                 : "=r"(r0), "=r"(r1), "=r"(r2), "=r"(r3) : "r"(addr));
}
__device__ __forceinline__ void ldmx4t(uint32_t& r0, uint32_t& r1, uint32_t& r2,
                                       uint32_t& r3, uint32_t addr) {
    asm volatile("ldmatrix.sync.aligned.m8n8.x4.trans.shared.b16 {%0,%1,%2,%3},[%4];\n"
                 : "=r"(r0), "=r"(r1), "=r"(r2), "=r"(r3) : "r"(addr));
}
__device__ __forceinline__ void mma16816(float c[4], uint32_t a0, uint32_t a1,
                                         uint32_t a2, uint32_t a3,
                                         uint32_t b0, uint32_t b1) {
    asm volatile(
        "mma.sync.aligned.m16n8k16.row.col.f32.f16.f16.f32 "
        "{%0,%1,%2,%3}, {%4,%5,%6,%7}, {%8,%9}, {%0,%1,%2,%3};"
        : "+f"(c[0]), "+f"(c[1]), "+f"(c[2]), "+f"(c[3])
        : "r"(a0), "r"(a1), "r"(a2), "r"(a3), "r"(b0), "r"(b1));
}

// FMA-pipe e^x, degree-3 (fexp(0) == 1.0 exactly).
__device__ __forceinline__ float fexp(float x) {
    x = fmaxf(x, -87.0f);
    const float L2E = 1.4426950408889634f;
    float t = fmaf(x, L2E, 12582912.0f);
    float i = t - 12582912.0f;
    float f = fmaf(x, L2E, -i);
    float p =            5.550357e-2f;
    p = fmaf(p, f, 2.402291e-1f);
    p = fmaf(p, f, 6.931406e-1f);
    p = fmaf(p, f, 1.0f);
    int eb = (__float_as_int(t) - 0x4B400000 + 127) << 23;
    return __int_as_float(eb) * p;
}

// ---------------- single fused weight transpose (fp16, paired stores) -------
#define QKV_TILES 18432
#define WP_END    24576
#define W1_END    49152
#define TOT_TILES 73728

__global__ __launch_bounds__(256) void wsplit_all(
    const float* __restrict__ Wq, const float* __restrict__ Wk,
    const float* __restrict__ Wv, const float* __restrict__ Wp,
    const float* __restrict__ W1, const float* __restrict__ W2)
{
    __shared__ float tbuf[32][33];
    const int t = blockIdx.x;
    const float* src; fp16 *dh;
    int K, N, n0, k0;
    if (t < QKV_TILES) {
        int z = t >> 10, r = t & 1023;
        int l = z / 3, wch = z % 3;
        src = (wch == 0 ? Wq : wch == 1 ? Wk : Wv) + (size_t)l * HH * HH;
        dh = w_qkv_h + (size_t)l * H3 * HH + (size_t)wch * HH * HH;
        K = HH; N = HH; n0 = (r & 31) * 32; k0 = (r >> 5) * 32;
    } else if (t < WP_END) {
        int t2 = t - QKV_TILES; int l = t2 >> 10, r = t2 & 1023;
        src = Wp + (size_t)l * HH * HH;
        dh = w_p_h + (size_t)l * HH * HH;
        K = HH; N = HH; n0 = (r & 31) * 32; k0 = (r >> 5) * 32;
    } else if (t < W1_END) {
        int t3 = t - WP_END; int l = t3 >> 12, r = t3 & 4095;
        src = W1 + (size_t)l * HH * FFF;
        dh = w_1_h + (size_t)l * FFF * HH;
        K = HH; N = FFF; n0 = (r & 127) * 32; k0 = (r >> 7) * 32;
    } else {
        int t4 = t - W1_END; int l = t4 >> 12, r = t4 & 4095;
        src = W2 + (size_t)l * FFF * HH;
        dh = w_2_h + (size_t)l * HH * FFF;
        K = FFF; N = HH; n0 = (r & 31) * 32; k0 = (r >> 5) * 32;
    }

    const int tx = threadIdx.x & 31, ty = threadIdx.x >> 5;
    #pragma unroll
    for (int u = 0; u < 4; u++)
        tbuf[ty + u * 8][tx] = src[(size_t)(k0 + ty + u * 8) * N + n0 + tx];
    __syncthreads();
    // paired-k 4-byte stores: thread (tx16, tyy) covers k pair 2*tx16, rows tyy + u*16
    const int tx16 = threadIdx.x & 15, tyy = threadIdx.x >> 4;
    #pragma unroll
    for (int u = 0; u < 2; u++) {
        const int nrel = tyy + u * 16;
        const float v0 = tbuf[2*tx16][nrel];
        const float v1 = tbuf[2*tx16 + 1][nrel];
        *(uint32_t*)(dh + (size_t)(n0 + nrel) * K + k0 + 2*tx16) = pk2(v0, v1);
    }
}

__global__ void prep_kernel(const float* __restrict__ in,
                            const float* bq, const float* bk, const float* bv)
{
    int id = blockIdx.x * blockDim.x + threadIdx.x;
    if (id < LL * H3) {
        int l = id / H3, c = id % H3;
        g_bqkv[id] = (c < HH) ? bq[l*HH + c]
                   : (c < 2*HH) ? bk[l*HH + c - HH] : bv[l*HH + c - 2*HH];
    }
    if (id < MM*HH/4) {
        float4 v = *(const float4*)(in + (size_t)id * 4);
        *(float4*)(g_x + (size_t)id * 4) = v;
        *(uint2*)(g_xh + (size_t)id * 4) =
            make_uint2(pk2(v.x, v.y), pk2(v.z, v.w));
    }
}

// ---------------- GEMM (fp16 1-term, BK=64, 256 thr, warp tile 64x32) --------
// epi: 1 bias+gelu->hi, 2 bias+resid->f32, 3 bias->hi (QKV: Q third scaled /8)
#define BK 64
#define SUBB 16384
#define STAGE_B (2*SUBB)
#define GEMM_SMEM (3*STAGE_B)

__device__ __forceinline__ uint32_t swz(int r, int c) {
    return (uint32_t)(r * 128 + ((c ^ (r & 7)) << 4));
}

__device__ __forceinline__ void ld_stage(
    uint32_t st, const fp16* Agh, const fp16* Bgh,
    int bm, int bn, int K, int k0, int tid)
{
    #pragma unroll
    for (int u = tid; u < 1024; u += 256) {
        const int r = u >> 3, c = u & 7;
        const uint32_t sw = swz(r, c);
        cp16(st + sw,         Agh + (size_t)(bm + r) * K + k0 + c * 8);
        cp16(st + SUBB + sw,  Bgh + (size_t)(bn + r) * K + k0 + c * 8);
    }
}

__global__ __launch_bounds__(256, 2) void gemm_kernel(
    const fp16* __restrict__ Agh, const fp16* __restrict__ Bgh,
    const float* __restrict__ bias, const float* __restrict__ resid,
    float* __restrict__ C, fp16* __restrict__ Ch,
    int M, int N, int K, int epi)
{
    extern __shared__ __align__(16) fp16 sm[];
    const int tid  = threadIdx.x;
    const int lane = tid & 31;
    const int wid  = tid >> 5;
    const int warp_m = wid & 1;
    const int warp_n = wid >> 1;
    const int bm = blockIdx.y * 128;
    const int bn = blockIdx.x * 128;
    const uint32_t smB = smem_u32(sm);

    float acc[4][4][4];
    #pragma unroll
    for (int i = 0; i < 4; i++)
        #pragma unroll
        for (int j = 0; j < 4; j++)
            #pragma unroll
            for (int u = 0; u < 4; u++) acc[i][j][u] = 0.f;

    const int ntiles = K / BK;

    ld_stage(smB, Agh, Bgh, bm, bn, K, 0, tid);
    asm volatile("cp.async.commit_group;\n");
    if (ntiles > 1)
        ld_stage(smB + STAGE_B, Agh, Bgh, bm, bn, K, BK, tid);
    asm volatile("cp.async.commit_group;\n");

    const int lr = lane & 15, lc = lane >> 4;

    for (int kt = 0; kt < ntiles; kt++) {
        asm volatile("cp.async.wait_group 1;\n");
        __syncthreads();

        const int nx = kt + 2;
        if (nx < ntiles)
            ld_stage(smB + (nx % 3) * STAGE_B, Agh, Bgh, bm, bn, K, nx * BK, tid);
        asm volatile("cp.async.commit_group;\n");

        const uint32_t st = smB + (kt % 3) * STAGE_B;
        const uint32_t Ah = st;
        const uint32_t Bh = st + SUBB;

        #pragma unroll
        for (int kk = 0; kk < 4; kk++) {
            const int cch = kk * 2 + lc;
            uint32_t a[4][4], bh[4][2];
            #pragma unroll
            for (int i = 0; i < 4; i++) {
                const int r_ = warp_m*64 + i*16 + lr;
                ldmx4(a[i][0], a[i][1], a[i][2], a[i][3], Ah + swz(r_, cch));
            }
            #pragma unroll
            for (int j16 = 0; j16 < 2; j16++) {
                const int rb_ = warp_n*32 + j16*16 + lr;
                uint32_t r0, r1, r2, r3;
                ldmx4(r0, r1, r2, r3, Bh + swz(rb_, cch));
                bh[j16*2][0] = r0; bh[j16*2][1] = r2;
                bh[j16*2+1][0] = r1; bh[j16*2+1][1] = r3;
            }
            #pragma unroll
            for (int i = 0; i < 4; i++)
                #pragma unroll
                for (int j = 0; j < 4; j++)
                    mma16816(acc[i][j], a[i][0],a[i][1],a[i][2],a[i][3], bh[j][0],bh[j][1]);
        }
    }

    #pragma unroll
    for (int i = 0; i < 4; i++) {
        #pragma unroll
        for (int j = 0; j < 4; j++) {
            const int row0 = bm + warp_m*64 + i*16 + (lane >> 2);
            const int col  = bn + warp_n*32 + j*8 + 2*(lane & 3);
            const float2 bv = *(const float2*)(bias + col);
            #pragma unroll
            for (int half_ = 0; half_ < 2; half_++) {
                const int row = row0 + half_ * 8;
                float rx = acc[i][j][half_*2+0] + bv.x;
                float ry = acc[i][j][half_*2+1] + bv.y;
                if (epi == 1) {
                    rx = 0.5f * rx * (1.0f + erff(rx * 0.70710678118654752f));
                    ry = 0.5f * ry * (1.0f + erff(ry * 0.70710678118654752f));
                    *(uint32_t*)(Ch + (size_t)row*N + col) = pk2(rx, ry);
                } else if (epi == 2) {
                    const float2 rv = *(const float2*)(resid + (size_t)row*N + col);
                    *(float2*)(C + (size_t)row*N + col) = make_float2(rx + rv.x, ry + rv.y);
                } else {
                    if (col < HH) { rx *= 0.125f; ry *= 0.125f; }
                    *(uint32_t*)(Ch + (size_t)row*N + col) = pk2(rx, ry);
                }
            }
        }
    }
}

// ---------------- causal flash attention -------------------------------------
#define AT_LDT 72
#define AQ_BYTES (128*AT_LDT*2)
#define AKV_BYTES (64*AT_LDT*2)
#define ATT_SMEM (AQ_BYTES + 4*AKV_BYTES)

__global__ __launch_bounds__(256, 2) void attn_kernel(const fp16* __restrict__ QKVh)
{
    extern __shared__ __align__(16) fp16 asmem[];
    const uint32_t sQ  = smem_u32(asmem);
    const uint32_t sK0 = sQ + AQ_BYTES;
    const uint32_t sV0 = sQ + AQ_BYTES + 2*AKV_BYTES;

    const int h   = blockIdx.y;
    const int b   = blockIdx.z;
    const int tid = threadIdx.x;
    const int w    = tid >> 5;
    const int lane = tid & 31;
    const int lr = lane & 15, lc = lane >> 4;
    const int rr = lane >> 2, cq = lane & 3;

    #pragma unroll 1
    for (int ph_ = 0; ph_ < 2; ph_++) {
        const int qtp = ph_ ? (TT/128 - 1 - blockIdx.x) : blockIdx.x;
        const int qb  = qtp * 128;
        const int nkt = 2 * qtp + 2;

        #pragma unroll
        for (int c = tid; c < 1024; c += 256) {
            int row = c >> 3, seg = c & 7;
            size_t g = ((size_t)(b*TT + qb + row))*H3 + h*DD + seg*8;
            cp16(sQ + (uint32_t)(row*AT_LDT + seg*8)*2, QKVh + g);
        }
        #pragma unroll
        for (int c = tid; c < 512; c += 256) {
            int row = c >> 3, seg = c & 7;
            size_t gk = ((size_t)(b*TT + row))*H3 + HH + h*DD + seg*8;
            uint32_t s = (uint32_t)(row*AT_LDT + seg*8)*2;
            cp16(sK0 + s, QKVh + gk);
            cp16(sV0 + s, QKVh + gk + HH);
        }
        asm volatile("cp.async.commit_group;\n");

        float O[8][4];
        #pragma unroll
        for (int j = 0; j < 8; j++)
            #pragma unroll
            for (int u = 0; u < 4; u++) O[j][u] = 0.f;
        float m0 = -1e30f, m1 = -1e30f, l0 = 0.f, l1 = 0.f;

        for (int kt = 0; kt < nkt; kt++) {
            if (kt + 1 < nkt) {
                const uint32_t sKp = sK0 + ((kt + 1) & 1) * AKV_BYTES;
                const uint32_t sVp = sV0 + ((kt + 1) & 1) * AKV_BYTES;
                #pragma unroll
                for (int c = tid; c < 512; c += 256) {
                    int row = c >> 3, seg = c & 7;
                    size_t gk = ((size_t)(b*TT + (kt+1)*64 + row))*H3 + HH + h*DD + seg*8;
                    uint32_t s = (uint32_t)(row*AT_LDT + seg*8)*2;
                    cp16(sKp + s, QKVh + gk);
                    cp16(sVp + s, QKVh + gk + HH);
                }
            }
            asm volatile("cp.async.commit_group;\n");
            asm volatile("cp.async.wait_group 1;\n");
            __syncthreads();

            const bool active = (kt * 64 <= qb + w*16 + 15);
            if (active) {
                const uint32_t sK = sK0 + (kt & 1) * AKV_BYTES;
                const uint32_t sV = sV0 + (kt & 1) * AKV_BYTES;

                float S[8][4];
                #pragma unroll
                for (int j = 0; j < 8; j++)
                    #pragma unroll
                    for (int u = 0; u < 4; u++) S[j][u] = 0.f;

                #pragma unroll
                for (int ks = 0; ks < 4; ks++) {
                    const uint32_t coff = (uint32_t)(ks*16 + lc*8)*2;
                    uint32_t qh[4];
                    ldmx4(qh[0], qh[1], qh[2], qh[3],
                          sQ + (uint32_t)((w*16 + lr)*AT_LDT)*2 + coff);
                    #pragma unroll
                    for (int j16 = 0; j16 < 4; j16++) {
                        uint32_t rb = (uint32_t)((j16*16 + lr)*AT_LDT)*2 + coff;
                        uint32_t k0,k1,k2,k3;
                        ldmx4(k0,k1,k2,k3, sK + rb);
                        mma16816(S[j16*2],   qh[0],qh[1],qh[2],qh[3], k0,k2);
                        mma16816(S[j16*2+1], qh[0],qh[1],qh[2],qh[3], k1,k3);
                    }
                }

                if (kt*64 + 63 > qb + w*16) {
                    const int q0 = qb + w*16 + rr, q1 = q0 + 8;
                    #pragma unroll
                    for (int j = 0; j < 8; j++) {
                        const int c0 = kt*64 + 8*j + 2*cq, c1 = c0 + 1;
                        if (c0 > q0) S[j][0] = -1e30f;
                        if (c1 > q0) S[j][1] = -1e30f;
                        if (c0 > q1) S[j][2] = -1e30f;
                        if (c1 > q1) S[j][3] = -1e30f;
                    }
                }

                float t0 = -1e30f, t1 = -1e30f;
                #pragma unroll
                for (int j = 0; j < 8; j++) {
                    t0 = fmaxf(t0, fmaxf(S[j][0], S[j][1]));
                    t1 = fmaxf(t1, fmaxf(S[j][2], S[j][3]));
                }
                t0 = fmaxf(t0, __shfl_xor_sync(0xffffffffu, t0, 1));
                t0 = fmaxf(t0, __shfl_xor_sync(0xffffffffu, t0, 2));
                t1 = fmaxf(t1, __shfl_xor_sync(0xffffffffu, t1, 1));
                t1 = fmaxf(t1, __shfl_xor_sync(0xffffffffu, t1, 2));

                // warp-uniform rescale skip when no row's max changed
                const bool upd = (t0 > m0) || (t1 > m1);
                if (__any_sync(0xffffffffu, upd)) {
                    const float n0 = fmaxf(m0, t0), n1 = fmaxf(m1, t1);
                    const float f0 = fexp(m0 - n0), f1 = fexp(m1 - n1);
                    m0 = n0; m1 = n1;
                    l0 *= f0; l1 *= f1;
                    #pragma unroll
                    for (int j = 0; j < 8; j++) {
                        O[j][0] *= f0; O[j][1] *= f0; O[j][2] *= f1; O[j][3] *= f1;
                    }
                }

                uint32_t ph2[8][2];
                float s0 = 0.f, s1 = 0.f;
                #pragma unroll
                for (int j = 0; j < 8; j++) {
                    float p0 = fexp(S[j][0] - m0), p1 = fexp(S[j][1] - m0);
                    float p2 = fexp(S[j][2] - m1), p3 = fexp(S[j][3] - m1);
                    s0 += p0 + p1; s1 += p2 + p3;
                    ph2[j][0] = pk2(p0, p1);
                    ph2[j][1] = pk2(p2, p3);
                }
                s0 += __shfl_xor_sync(0xffffffffu, s0, 1);
                s0 += __shfl_xor_sync(0xffffffffu, s0, 2);
                s1 += __shfl_xor_sync(0xffffffffu, s1, 1);
                s1 += __shfl_xor_sync(0xffffffffu, s1, 2);
                l0 += s0; l1 += s1;

                #pragma unroll
                for (int ks = 0; ks < 4; ks++) {
                    uint32_t a0 = ph2[2*ks][0], a1 = ph2[2*ks][1],
                             a2 = ph2[2*ks+1][0], a3 = ph2[2*ks+1][1];
                    #pragma unroll
                    for (int j16 = 0; j16 < 4; j16++) {
                        uint32_t rbv = (uint32_t)((ks*16 + lr)*AT_LDT + j16*16 + lc*8)*2;
                        uint32_t v0,v1,v2,v3;
                        ldmx4t(v0,v1,v2,v3, sV + rbv);
                        mma16816(O[2*j16],   a0,a1,a2,a3, v0,v1);
                        mma16816(O[2*j16+1], a0,a1,a2,a3, v2,v3);
                    }
                }
            }
            __syncthreads();
        }

        const float inv0 = 1.f / l0, inv1 = 1.f / l1;
        const size_t row0 = (size_t)(b*TT + qb + w*16 + rr);
        const size_t row1 = row0 + 8;
        #pragma unroll
        for (int j = 0; j < 8; j++) {
            const int col = h*DD + 8*j + 2*cq;
            *(uint32_t*)(g_oh + row0*HH + col) = pk2(O[j][0]*inv0, O[j][1]*inv0);
            *(uint32_t*)(g_oh + row1*HH + col) = pk2(O[j][2]*inv1, O[j][3]*inv1);
        }
        __syncthreads();
    }
}

// ---------------- LayerNorm (warp-shuffle reduction) -------------------------
__global__ __launch_bounds__(256) void ln_kernel(
    const float* __restrict__ in, const float* __restrict__ gamma,
    const float* __restrict__ beta, float* __restrict__ out,
    fp16* __restrict__ outh)
{
    __shared__ float ws[8], ws2[8];
    const int row = blockIdx.x;
    const int tid = threadIdx.x;
    const int lane = tid & 31, wid = tid >> 5;
    const float* p = in + (size_t)row * HH;

    float4 v = *(const float4*)(p + tid * 4);
    float s = v.x + v.y + v.z + v.w;
    float q = v.x*v.x + v.y*v.y + v.z*v.z + v.w*v.w;
    #pragma unroll
    for (int off = 16; off > 0; off >>= 1) {
        s += __shfl_xor_sync(0xffffffffu, s, off);
        q += __shfl_xor_sync(0xffffffffu, q, off);
    }
    if (lane == 0) { ws[wid] = s; ws2[wid] = q; }
    __syncthreads();
    float ts = 0.f, tq = 0.f;
    #pragma unroll
    for (int u = 0; u < 8; u++) { ts += ws[u]; tq += ws2[u]; }
    const float mean = ts * (1.0f / HH);
    const float var  = tq * (1.0f / HH) - mean * mean;
    const float rstd = rsqrtf(var + 1e-5f);

    float dx = v.x-mean, dy = v.y-mean, dz = v.z-mean, dw = v.w-mean;
    float4 g  = *(const float4*)(gamma + tid * 4);
    float4 be = *(const float4*)(beta + tid * 4);
    float4 rr;
    rr.x = dx*rstd*g.x + be.x;
    rr.y = dy*rstd*g.y + be.y;
    rr.z = dz*rstd*g.z + be.z;
    rr.w = dw*rstd*g.w + be.w;
    *(float4*)(out + (size_t)row*HH + tid*4) = rr;
    *(uint2*)(outh + (size_t)row*HH + tid*4) =
        make_uint2(pk2(rr.x, rr.y), pk2(rr.z, rr.w));
}

// ---------------- launcher -------------------------------------------------
extern "C" void kernel_launch(void* const* d_in, const int* in_sizes, int n_in,
                              void* d_out, int out_size)
{
    const float* Wq  = (const float*)d_in[1];
    const float* bq  = (const float*)d_in[2];
    const float* Wk  = (const float*)d_in[3];
    const float* bk  = (const float*)d_in[4];
    const float* Wv  = (const float*)d_in[5];
    const float* bv  = (const float*)d_in[6];
    const float* Wp  = (const float*)d_in[7];
    const float* bp  = (const float*)d_in[8];
    const float* W1  = (const float*)d_in[9];
    const float* b1  = (const float*)d_in[10];
    const float* W2  = (const float*)d_in[11];
    const float* b2  = (const float*)d_in[12];
    const float* g1w = (const float*)d_in[13];
    const float* be1 = (const float*)d_in[14];
    const float* g2w = (const float*)d_in[15];
    const float* be2 = (const float*)d_in[16];

    cudaFuncSetAttribute(gemm_kernel, cudaFuncAttributeMaxDynamicSharedMemorySize, GEMM_SMEM);
    cudaFuncSetAttribute(attn_kernel, cudaFuncAttributeMaxDynamicSharedMemorySize, ATT_SMEM);

    float *gx, *gt, *gbqkv;
    fp16 *gxh, *gqkvh, *goh, *ghh;
    fp16 *wqh, *wph, *w1h, *w2h;
    cudaGetSymbolAddress((void**)&gx,    g_x);
    cudaGetSymbolAddress((void**)&gxh,   g_xh);
    cudaGetSymbolAddress((void**)&gqkvh, g_qkvh);
    cudaGetSymbolAddress((void**)&goh,   g_oh);
    cudaGetSymbolAddress((void**)&gt,    g_t);
    cudaGetSymbolAddress((void**)&ghh,   g_hh);
    cudaGetSymbolAddress((void**)&wqh,   w_qkv_h);
    cudaGetSymbolAddress((void**)&wph,   w_p_h);
    cudaGetSymbolAddress((void**)&w1h,   w_1_h);
    cudaGetSymbolAddress((void**)&w2h,   w_2_h);
    cudaGetSymbolAddress((void**)&gbqkv, g_bqkv);

    wsplit_all<<<TOT_TILES, 256>>>(Wq, Wk, Wv, Wp, W1, W2);
    prep_kernel<<<(MM*HH/4 + 255)/256, 256>>>((const float*)d_in[0], bq, bk, bv);

    const dim3 gridQKV(H3/128, MM/128);
    const dim3 gridH(HH/128, MM/128);
    const dim3 gridF(FFF/128, MM/128);
    const dim3 gridA(TT/256, NHH, BB);

    for (int l = 0; l < LL; l++) {
        const size_t bo = (size_t)l * HH;

        gemm_kernel<<<gridQKV, 256, GEMM_SMEM>>>(
            gxh, wqh + (size_t)l*H3*HH,
            gbqkv + (size_t)l*H3, nullptr, nullptr, gqkvh,
            MM, H3, HH, 3);

        attn_kernel<<<gridA, 256, ATT_SMEM>>>(gqkvh);

        gemm_kernel<<<gridH, 256, GEMM_SMEM>>>(
            goh, wph + (size_t)l*HH*HH,
            bp + bo, gx, gt, nullptr, MM, HH, HH, 2);
        ln_kernel<<<MM, 256>>>(gt, g1w + bo, be1 + bo, gx, gxh);

        gemm_kernel<<<gridF, 256, GEMM_SMEM>>>(
            gxh, w1h + (size_t)l*FFF*HH,
            b1 + (size_t)l*FFF, nullptr, nullptr, ghh, MM, FFF, HH, 1);
        gemm_kernel<<<gridH, 256, GEMM_SMEM>>>(
            ghh, w2h + (size_t)l*HH*FFF,
            b2 + bo, gx, gt, nullptr, MM, HH, FFF, 2);
        ln_kernel<<<MM, 256>>>(gt, g2w + bo, be2 + bo, gx, gxh);
    }

    cudaMemcpyAsync(d_out, gx, (size_t)MM*HH*sizeof(float),
                    cudaMemcpyDeviceToDevice, 0);
}

// round 16
// speedup vs baseline: 1.5580x; 1.0291x over previous
#include <cuda_runtime.h>
#include <cuda_fp16.h>
#include <math.h>
#include <stdint.h>

#define BB 2
#define TT 2048
#define HH 1024
#define NHH 16
#define DD 64
#define FFF 4096
#define LL 6
#define MM (BB*TT)
#define H3 (3*HH)

typedef __half fp16;

// ---------------- device-global scratch ------------------------------------
__device__ float g_x [MM*HH];
__device__ fp16  g_xh[MM*HH];
__device__ fp16  g_qkvh[MM*H3];
__device__ fp16  g_oh[MM*HH];
__device__ float g_t [MM*HH];
__device__ fp16  g_hh[MM*FFF];
__device__ fp16  w_qkv_h[LL*H3*HH];
__device__ fp16  w_p_h  [LL*HH*HH];
__device__ fp16  w_1_h  [LL*FFF*HH];
__device__ fp16  w_2_h  [LL*HH*FFF];
__device__ float g_bqkv[LL*H3];

// ---------------- helpers ---------------------------------------------------
__device__ __forceinline__ uint32_t pk2(float a, float b) {
    __half2 h = __floats2half2_rn(a, b);
    return *(uint32_t*)&h;
}
__device__ __forceinline__ uint32_t smem_u32(const void* p) {
    return (uint32_t)__cvta_generic_to_shared(p);
}
__device__ __forceinline__ void cp16(uint32_t s, const void* g) {
    asm volatile("cp.async.cg.shared.global [%0],[%1],16;\n" :: "r"(s), "l"(g));
}
__device__ __forceinline__ void ldmx4(uint32_t& r0, uint32_t& r1, uint32_t& r2,
                                      uint32_t& r3, uint32_t addr) {
    asm volatile("ldmatrix.sync.aligned.m8n8.x4.shared.b16 {%0,%1,%2,%3},[%4];\n"
                 : "=r"(r0), "=r"(r1), "=r"(r2), "=r"(r3) : "r"(addr));
}
__device__ __forceinline__ void ldmx4t(uint32_t& r0, uint32_t& r1, uint32_t& r2,
                                       uint32_t& r3, uint32_t addr) {
    asm volatile("ldmatrix.sync.aligned.m8n8.x4.trans.shared.b16 {%0,%1,%2,%3},[%4];\n"
                 : "=r"(r0), "=r"(r1), "=r"(r2), "=r"(r3) : "r"(addr));
}
__device__ __forceinline__ void mma16816(float c[4], uint32_t a0, uint32_t a1,
                                         uint32_t a2, uint32_t a3,
                                         uint32_t b0, uint32_t b1) {
    asm volatile(
        "mma.sync.aligned.m16n8k16.row.col.f32.f16.f16.f32 "
        "{%0,%1,%2,%3}, {%4,%5,%6,%7}, {%8,%9}, {%0,%1,%2,%3};"
        : "+f"(c[0]), "+f"(c[1]), "+f"(c[2]), "+f"(c[3])
        : "r"(a0), "r"(a1), "r"(a2), "r"(a3), "r"(b0), "r"(b1));
}

// FMA-pipe e^x, degree-3 (fexp(0) == 1.0 exactly).
__device__ __forceinline__ float fexp(float x) {
    x = fmaxf(x, -87.0f);
    const float L2E = 1.4426950408889634f;
    float t = fmaf(x, L2E, 12582912.0f);
    float i = t - 12582912.0f;
    float f = fmaf(x, L2E, -i);
    float p =            5.550357e-2f;
    p = fmaf(p, f, 2.402291e-1f);
    p = fmaf(p, f, 6.931406e-1f);
    p = fmaf(p, f, 1.0f);
    int eb = (__float_as_int(t) - 0x4B400000 + 127) << 23;
    return __int_as_float(eb) * p;
}

// FMA-only reciprocal (bit trick + 3 Newton steps), valid for normal d > 0.
__device__ __forceinline__ float frcp_fma(float d) {
    float y = __int_as_float(0x7EF311C3 - __float_as_int(d));
    y *= fmaf(-d, y, 2.0f);
    y *= fmaf(-d, y, 2.0f);
    y *= fmaf(-d, y, 2.0f);
    return y;
}

// Exact-enough GELU: 0.5x(1+erf(x/sqrt2)), erf via A&S 7.1.26 (abs err 1.5e-7).
// No MUFU, no branches.
__device__ __forceinline__ float gelu(float x) {
    const float z  = x * 0.70710678118654752f;
    const float az = fminf(fabsf(z), 10.0f);
    const float t  = frcp_fma(fmaf(0.3275911f, az, 1.0f));
    float p =            1.061405429f;
    p = fmaf(p, t, -1.453152027f);
    p = fmaf(p, t,  1.421413741f);
    p = fmaf(p, t, -0.284496736f);
    p = fmaf(p, t,  0.254829592f);
    const float e = fexp(-az * az);
    float erf_abs = fmaf(-p * t, e, 1.0f);
    float erf = (z < 0.f) ? -erf_abs : erf_abs;
    return 0.5f * x * (1.0f + erf);
}

// ---------------- single fused weight transpose (fp16, paired stores) -------
#define QKV_TILES 18432
#define WP_END    24576
#define W1_END    49152
#define TOT_TILES 73728

__global__ __launch_bounds__(256) void wsplit_all(
    const float* __restrict__ Wq, const float* __restrict__ Wk,
    const float* __restrict__ Wv, const float* __restrict__ Wp,
    const float* __restrict__ W1, const float* __restrict__ W2)
{
    __shared__ float tbuf[32][33];
    const int t = blockIdx.x;
    const float* src; fp16 *dh;
    int K, N, n0, k0;
    if (t < QKV_TILES) {
        int z = t >> 10, r = t & 1023;
        int l = z / 3, wch = z % 3;
        src = (wch == 0 ? Wq : wch == 1 ? Wk : Wv) + (size_t)l * HH * HH;
        dh = w_qkv_h + (size_t)l * H3 * HH + (size_t)wch * HH * HH;
        K = HH; N = HH; n0 = (r & 31) * 32; k0 = (r >> 5) * 32;
    } else if (t < WP_END) {
        int t2 = t - QKV_TILES; int l = t2 >> 10, r = t2 & 1023;
        src = Wp + (size_t)l * HH * HH;
        dh = w_p_h + (size_t)l * HH * HH;
        K = HH; N = HH; n0 = (r & 31) * 32; k0 = (r >> 5) * 32;
    } else if (t < W1_END) {
        int t3 = t - WP_END; int l = t3 >> 12, r = t3 & 4095;
        src = W1 + (size_t)l * HH * FFF;
        dh = w_1_h + (size_t)l * FFF * HH;
        K = HH; N = FFF; n0 = (r & 127) * 32; k0 = (r >> 7) * 32;
    } else {
        int t4 = t - W1_END; int l = t4 >> 12, r = t4 & 4095;
        src = W2 + (size_t)l * FFF * HH;
        dh = w_2_h + (size_t)l * HH * FFF;
        K = FFF; N = HH; n0 = (r & 31) * 32; k0 = (r >> 5) * 32;
    }

    const int tx = threadIdx.x & 31, ty = threadIdx.x >> 5;
    #pragma unroll
    for (int u = 0; u < 4; u++)
        tbuf[ty + u * 8][tx] = src[(size_t)(k0 + ty + u * 8) * N + n0 + tx];
    __syncthreads();
    const int tx16 = threadIdx.x & 15, tyy = threadIdx.x >> 4;
    #pragma unroll
    for (int u = 0; u < 2; u++) {
        const int nrel = tyy + u * 16;
        const float v0 = tbuf[2*tx16][nrel];
        const float v1 = tbuf[2*tx16 + 1][nrel];
        *(uint32_t*)(dh + (size_t)(n0 + nrel) * K + k0 + 2*tx16) = pk2(v0, v1);
    }
}

__global__ void prep_kernel(const float* __restrict__ in,
                            const float* bq, const float* bk, const float* bv)
{
    int id = blockIdx.x * blockDim.x + threadIdx.x;
    if (id < LL * H3) {
        int l = id / H3, c = id % H3;
        g_bqkv[id] = (c < HH) ? bq[l*HH + c]
                   : (c < 2*HH) ? bk[l*HH + c - HH] : bv[l*HH + c - 2*HH];
    }
    if (id < MM*HH/4) {
        float4 v = *(const float4*)(in + (size_t)id * 4);
        *(float4*)(g_x + (size_t)id * 4) = v;
        *(uint2*)(g_xh + (size_t)id * 4) =
            make_uint2(pk2(v.x, v.y), pk2(v.z, v.w));
    }
}

// ---------------- GEMM (fp16 1-term, BK=64, 256 thr, warp tile 64x32) --------
// epi: 1 bias+gelu->hi, 2 bias+resid->f32, 3 bias->hi (QKV: Q third scaled /8)
#define BK 64
#define SUBB 16384
#define STAGE_B (2*SUBB)
#define GEMM_SMEM (3*STAGE_B)

__device__ __forceinline__ uint32_t swz(int r, int c) {
    return (uint32_t)(r * 128 + ((c ^ (r & 7)) << 4));
}

__device__ __forceinline__ void ld_stage(
    uint32_t st, const fp16* Agh, const fp16* Bgh,
    int bm, int bn, int K, int k0, int tid)
{
    #pragma unroll
    for (int u = tid; u < 1024; u += 256) {
        const int r = u >> 3, c = u & 7;
        const uint32_t sw = swz(r, c);
        cp16(st + sw,         Agh + (size_t)(bm + r) * K + k0 + c * 8);
        cp16(st + SUBB + sw,  Bgh + (size_t)(bn + r) * K + k0 + c * 8);
    }
}

__global__ __launch_bounds__(256, 2) void gemm_kernel(
    const fp16* __restrict__ Agh, const fp16* __restrict__ Bgh,
    const float* __restrict__ bias, const float* __restrict__ resid,
    float* __restrict__ C, fp16* __restrict__ Ch,
    int M, int N, int K, int epi)
{
    extern __shared__ __align__(16) fp16 sm[];
    const int tid  = threadIdx.x;
    const int lane = tid & 31;
    const int wid  = tid >> 5;
    const int warp_m = wid & 1;
    const int warp_n = wid >> 1;
    const int bm = blockIdx.y * 128;
    const int bn = blockIdx.x * 128;
    const uint32_t smB = smem_u32(sm);

    float acc[4][4][4];
    #pragma unroll
    for (int i = 0; i < 4; i++)
        #pragma unroll
        for (int j = 0; j < 4; j++)
            #pragma unroll
            for (int u = 0; u < 4; u++) acc[i][j][u] = 0.f;

    const int ntiles = K / BK;

    ld_stage(smB, Agh, Bgh, bm, bn, K, 0, tid);
    asm volatile("cp.async.commit_group;\n");
    if (ntiles > 1)
        ld_stage(smB + STAGE_B, Agh, Bgh, bm, bn, K, BK, tid);
    asm volatile("cp.async.commit_group;\n");

    const int lr = lane & 15, lc = lane >> 4;

    for (int kt = 0; kt < ntiles; kt++) {
        asm volatile("cp.async.wait_group 1;\n");
        __syncthreads();

        const int nx = kt + 2;
        if (nx < ntiles)
            ld_stage(smB + (nx % 3) * STAGE_B, Agh, Bgh, bm, bn, K, nx * BK, tid);
        asm volatile("cp.async.commit_group;\n");

        const uint32_t st = smB + (kt % 3) * STAGE_B;
        const uint32_t Ah = st;
        const uint32_t Bh = st + SUBB;

        #pragma unroll
        for (int kk = 0; kk < 4; kk++) {
            const int cch = kk * 2 + lc;
            uint32_t a[4][4], bh[4][2];
            #pragma unroll
            for (int i = 0; i < 4; i++) {
                const int r_ = warp_m*64 + i*16 + lr;
                ldmx4(a[i][0], a[i][1], a[i][2], a[i][3], Ah + swz(r_, cch));
            }
            #pragma unroll
            for (int j16 = 0; j16 < 2; j16++) {
                const int rb_ = warp_n*32 + j16*16 + lr;
                uint32_t r0, r1, r2, r3;
                ldmx4(r0, r1, r2, r3, Bh + swz(rb_, cch));
                bh[j16*2][0] = r0; bh[j16*2][1] = r2;
                bh[j16*2+1][0] = r1; bh[j16*2+1][1] = r3;
            }
            #pragma unroll
            for (int i = 0; i < 4; i++)
                #pragma unroll
                for (int j = 0; j < 4; j++)
                    mma16816(acc[i][j], a[i][0],a[i][1],a[i][2],a[i][3], bh[j][0],bh[j][1]);
        }
    }

    #pragma unroll
    for (int i = 0; i < 4; i++) {
        #pragma unroll
        for (int j = 0; j < 4; j++) {
            const int row0 = bm + warp_m*64 + i*16 + (lane >> 2);
            const int col  = bn + warp_n*32 + j*8 + 2*(lane & 3);
            const float2 bv = *(const float2*)(bias + col);
            #pragma unroll
            for (int half_ = 0; half_ < 2; half_++) {
                const int row = row0 + half_ * 8;
                float rx = acc[i][j][half_*2+0] + bv.x;
                float ry = acc[i][j][half_*2+1] + bv.y;
                if (epi == 1) {
                    rx = gelu(rx);
                    ry = gelu(ry);
                    *(uint32_t*)(Ch + (size_t)row*N + col) = pk2(rx, ry);
                } else if (epi == 2) {
                    const float2 rv = *(const float2*)(resid + (size_t)row*N + col);
                    *(float2*)(C + (size_t)row*N + col) = make_float2(rx + rv.x, ry + rv.y);
                } else {
                    if (col < HH) { rx *= 0.125f; ry *= 0.125f; }
                    *(uint32_t*)(Ch + (size_t)row*N + col) = pk2(rx, ry);
                }
            }
        }
    }
}

// ---------------- causal flash attention -------------------------------------
#define AT_LDT 72
#define AQ_BYTES (128*AT_LDT*2)
#define AKV_BYTES (64*AT_LDT*2)
#define ATT_SMEM (AQ_BYTES + 4*AKV_BYTES)

__global__ __launch_bounds__(256, 2) void attn_kernel(const fp16* __restrict__ QKVh)
{
    extern __shared__ __align__(16) fp16 asmem[];
    const uint32_t sQ  = smem_u32(asmem);
    const uint32_t sK0 = sQ + AQ_BYTES;
    const uint32_t sV0 = sQ + AQ_BYTES + 2*AKV_BYTES;

    const int h   = blockIdx.y;
    const int b   = blockIdx.z;
    const int tid = threadIdx.x;
    const int w    = tid >> 5;
    const int lane = tid & 31;
    const int lr = lane & 15, lc = lane >> 4;
    const int rr = lane >> 2, cq = lane & 3;

    #pragma unroll 1
    for (int ph_ = 0; ph_ < 2; ph_++) {
        const int qtp = ph_ ? (TT/128 - 1 - blockIdx.x) : blockIdx.x;
        const int qb  = qtp * 128;
        const int nkt = 2 * qtp + 2;

        #pragma unroll
        for (int c = tid; c < 1024; c += 256) {
            int row = c >> 3, seg = c & 7;
            size_t g = ((size_t)(b*TT + qb + row))*H3 + h*DD + seg*8;
            cp16(sQ + (uint32_t)(row*AT_LDT + seg*8)*2, QKVh + g);
        }
        #pragma unroll
        for (int c = tid; c < 512; c += 256) {
            int row = c >> 3, seg = c & 7;
            size_t gk = ((size_t)(b*TT + row))*H3 + HH + h*DD + seg*8;
            uint32_t s = (uint32_t)(row*AT_LDT + seg*8)*2;
            cp16(sK0 + s, QKVh + gk);
            cp16(sV0 + s, QKVh + gk + HH);
        }
        asm volatile("cp.async.commit_group;\n");

        float O[8][4];
        #pragma unroll
        for (int j = 0; j < 8; j++)
            #pragma unroll
            for (int u = 0; u < 4; u++) O[j][u] = 0.f;
        float m0 = -1e30f, m1 = -1e30f, l0 = 0.f, l1 = 0.f;

        for (int kt = 0; kt < nkt; kt++) {
            if (kt + 1 < nkt) {
                const uint32_t sKp = sK0 + ((kt + 1) & 1) * AKV_BYTES;
                const uint32_t sVp = sV0 + ((kt + 1) & 1) * AKV_BYTES;
                #pragma unroll
                for (int c = tid; c < 512; c += 256) {
                    int row = c >> 3, seg = c & 7;
                    size_t gk = ((size_t)(b*TT + (kt+1)*64 + row))*H3 + HH + h*DD + seg*8;
                    uint32_t s = (uint32_t)(row*AT_LDT + seg*8)*2;
                    cp16(sKp + s, QKVh + gk);
                    cp16(sVp + s, QKVh + gk + HH);
                }
            }
            asm volatile("cp.async.commit_group;\n");
            asm volatile("cp.async.wait_group 1;\n");
            __syncthreads();

            const bool active = (kt * 64 <= qb + w*16 + 15);
            if (active) {
                const uint32_t sK = sK0 + (kt & 1) * AKV_BYTES;
                const uint32_t sV = sV0 + (kt & 1) * AKV_BYTES;

                float S[8][4];
                #pragma unroll
                for (int j = 0; j < 8; j++)
                    #pragma unroll
                    for (int u = 0; u < 4; u++) S[j][u] = 0.f;

                #pragma unroll
                for (int ks = 0; ks < 4; ks++) {
                    const uint32_t coff = (uint32_t)(ks*16 + lc*8)*2;
                    uint32_t qh[4];
                    ldmx4(qh[0], qh[1], qh[2], qh[3],
                          sQ + (uint32_t)((w*16 + lr)*AT_LDT)*2 + coff);
                    #pragma unroll
                    for (int j16 = 0; j16 < 4; j16++) {
                        uint32_t rb = (uint32_t)((j16*16 + lr)*AT_LDT)*2 + coff;
                        uint32_t k0,k1,k2,k3;
                        ldmx4(k0,k1,k2,k3, sK + rb);
                        mma16816(S[j16*2],   qh[0],qh[1],qh[2],qh[3], k0,k2);
                        mma16816(S[j16*2+1], qh[0],qh[1],qh[2],qh[3], k1,k3);
                    }
                }

                if (kt*64 + 63 > qb + w*16) {
                    const int q0 = qb + w*16 + rr, q1 = q0 + 8;
                    #pragma unroll
                    for (int j = 0; j < 8; j++) {
                        const int c0 = kt*64 + 8*j + 2*cq, c1 = c0 + 1;
                        if (c0 > q0) S[j][0] = -1e30f;
                        if (c1 > q0) S[j][1] = -1e30f;
                        if (c0 > q1) S[j][2] = -1e30f;
                        if (c1 > q1) S[j][3] = -1e30f;
                    }
                }

                float t0 = -1e30f, t1 = -1e30f;
                #pragma unroll
                for (int j = 0; j < 8; j++) {
                    t0 = fmaxf(t0, fmaxf(S[j][0], S[j][1]));
                    t1 = fmaxf(t1, fmaxf(S[j][2], S[j][3]));
                }
                t0 = fmaxf(t0, __shfl_xor_sync(0xffffffffu, t0, 1));
                t0 = fmaxf(t0, __shfl_xor_sync(0xffffffffu, t0, 2));
                t1 = fmaxf(t1, __shfl_xor_sync(0xffffffffu, t1, 1));
                t1 = fmaxf(t1, __shfl_xor_sync(0xffffffffu, t1, 2));

                const bool upd = (t0 > m0) || (t1 > m1);
                if (__any_sync(0xffffffffu, upd)) {
                    const float n0 = fmaxf(m0, t0), n1 = fmaxf(m1, t1);
                    const float f0 = fexp(m0 - n0), f1 = fexp(m1 - n1);
                    m0 = n0; m1 = n1;
                    l0 *= f0; l1 *= f1;
                    #pragma unroll
                    for (int j = 0; j < 8; j++) {
                        O[j][0] *= f0; O[j][1] *= f0; O[j][2] *= f1; O[j][3] *= f1;
                    }
                }

                uint32_t ph2[8][2];
                float s0 = 0.f, s1 = 0.f;
                #pragma unroll
                for (int j = 0; j < 8; j++) {
                    float p0 = fexp(S[j][0] - m0), p1 = fexp(S[j][1] - m0);
                    float p2 = fexp(S[j][2] - m1), p3 = fexp(S[j][3] - m1);
                    s0 += p0 + p1; s1 += p2 + p3;
                    ph2[j][0] = pk2(p0, p1);
                    ph2[j][1] = pk2(p2, p3);
                }
                s0 += __shfl_xor_sync(0xffffffffu, s0, 1);
                s0 += __shfl_xor_sync(0xffffffffu, s0, 2);
                s1 += __shfl_xor_sync(0xffffffffu, s1, 1);
                s1 += __shfl_xor_sync(0xffffffffu, s1, 2);
                l0 += s0; l1 += s1;

                #pragma unroll
                for (int ks = 0; ks < 4; ks++) {
                    uint32_t a0 = ph2[2*ks][0], a1 = ph2[2*ks][1],
                             a2 = ph2[2*ks+1][0], a3 = ph2[2*ks+1][1];
                    #pragma unroll
                    for (int j16 = 0; j16 < 4; j16++) {
                        uint32_t rbv = (uint32_t)((ks*16 + lr)*AT_LDT + j16*16 + lc*8)*2;
                        uint32_t v0,v1,v2,v3;
                        ldmx4t(v0,v1,v2,v3, sV + rbv);
                        mma16816(O[2*j16],   a0,a1,a2,a3, v0,v1);
                        mma16816(O[2*j16+1], a0,a1,a2,a3, v2,v3);
                    }
                }
            }
            __syncthreads();
        }

        const float inv0 = 1.f / l0, inv1 = 1.f / l1;
        const size_t row0 = (size_t)(b*TT + qb + w*16 + rr);
        const size_t row1 = row0 + 8;
        #pragma unroll
        for (int j = 0; j < 8; j++) {
            const int col = h*DD + 8*j + 2*cq;
            *(uint32_t*)(g_oh + row0*HH + col) = pk2(O[j][0]*inv0, O[j][1]*inv0);
            *(uint32_t*)(g_oh + row1*HH + col) = pk2(O[j][2]*inv1, O[j][3]*inv1);
        }
        __syncthreads();
    }
}

// ---------------- LayerNorm (warp-shuffle reduction) -------------------------
__global__ __launch_bounds__(256) void ln_kernel(
    const float* __restrict__ in, const float* __restrict__ gamma,
    const float* __restrict__ beta, float* __restrict__ out,
    fp16* __restrict__ outh)
{
    __shared__ float ws[8], ws2[8];
    const int row = blockIdx.x;
    const int tid = threadIdx.x;
    const int lane = tid & 31, wid = tid >> 5;
    const float* p = in + (size_t)row * HH;

    float4 v = *(const float4*)(p + tid * 4);
    float s = v.x + v.y + v.z + v.w;
    float q = v.x*v.x + v.y*v.y + v.z*v.z + v.w*v.w;
    #pragma unroll
    for (int off = 16; off > 0; off >>= 1) {
        s += __shfl_xor_sync(0xffffffffu, s, off);
        q += __shfl_xor_sync(0xffffffffu, q, off);
    }
    if (lane == 0) { ws[wid] = s; ws2[wid] = q; }
    __syncthreads();
    float ts = 0.f, tq = 0.f;
    #pragma unroll
    for (int u = 0; u < 8; u++) { ts += ws[u]; tq += ws2[u]; }
    const float mean = ts * (1.0f / HH);
    const float var  = tq * (1.0f / HH) - mean * mean;
    const float rstd = rsqrtf(var + 1e-5f);

    float dx = v.x-mean, dy = v.y-mean, dz = v.z-mean, dw = v.w-mean;
    float4 g  = *(const float4*)(gamma + tid * 4);
    float4 be = *(const float4*)(beta + tid * 4);
    float4 rr;
    rr.x = dx*rstd*g.x + be.x;
    rr.y = dy*rstd*g.y + be.y;
    rr.z = dz*rstd*g.z + be.z;
    rr.w = dw*rstd*g.w + be.w;
    *(float4*)(out + (size_t)row*HH + tid*4) = rr;
    *(uint2*)(outh + (size_t)row*HH + tid*4) =
        make_uint2(pk2(rr.x, rr.y), pk2(rr.z, rr.w));
}

// ---------------- launcher -------------------------------------------------
extern "C" void kernel_launch(void* const* d_in, const int* in_sizes, int n_in,
                              void* d_out, int out_size)
{
    const float* Wq  = (const float*)d_in[1];
    const float* bq  = (const float*)d_in[2];
    const float* Wk  = (const float*)d_in[3];
    const float* bk  = (const float*)d_in[4];
    const float* Wv  = (const float*)d_in[5];
    const float* bv  = (const float*)d_in[6];
    const float* Wp  = (const float*)d_in[7];
    const float* bp  = (const float*)d_in[8];
    const float* W1  = (const float*)d_in[9];
    const float* b1  = (const float*)d_in[10];
    const float* W2  = (const float*)d_in[11];
    const float* b2  = (const float*)d_in[12];
    const float* g1w = (const float*)d_in[13];
    const float* be1 = (const float*)d_in[14];
    const float* g2w = (const float*)d_in[15];
    const float* be2 = (const float*)d_in[16];

    cudaFuncSetAttribute(gemm_kernel, cudaFuncAttributeMaxDynamicSharedMemorySize, GEMM_SMEM);
    cudaFuncSetAttribute(attn_kernel, cudaFuncAttributeMaxDynamicSharedMemorySize, ATT_SMEM);

    float *gx, *gt, *gbqkv;
    fp16 *gxh, *gqkvh, *goh, *ghh;
    fp16 *wqh, *wph, *w1h, *w2h;
    cudaGetSymbolAddress((void**)&gx,    g_x);
    cudaGetSymbolAddress((void**)&gxh,   g_xh);
    cudaGetSymbolAddress((void**)&gqkvh, g_qkvh);
    cudaGetSymbolAddress((void**)&goh,   g_oh);
    cudaGetSymbolAddress((void**)&gt,    g_t);
    cudaGetSymbolAddress((void**)&ghh,   g_hh);
    cudaGetSymbolAddress((void**)&wqh,   w_qkv_h);
    cudaGetSymbolAddress((void**)&wph,   w_p_h);
    cudaGetSymbolAddress((void**)&w1h,   w_1_h);
    cudaGetSymbolAddress((void**)&w2h,   w_2_h);
    cudaGetSymbolAddress((void**)&gbqkv, g_bqkv);

    wsplit_all<<<TOT_TILES, 256>>>(Wq, Wk, Wv, Wp, W1, W2);
    prep_kernel<<<(MM*HH/4 + 255)/256, 256>>>((const float*)d_in[0], bq, bk, bv);

    const dim3 gridQKV(H3/128, MM/128);
    const dim3 gridH(HH/128, MM/128);
    const dim3 gridF(FFF/128, MM/128);
    const dim3 gridA(TT/256, NHH, BB);

    for (int l = 0; l < LL; l++) {
        const size_t bo = (size_t)l * HH;

        gemm_kernel<<<gridQKV, 256, GEMM_SMEM>>>(
            gxh, wqh + (size_t)l*H3*HH,
            gbqkv + (size_t)l*H3, nullptr, nullptr, gqkvh,
            MM, H3, HH, 3);

        attn_kernel<<<gridA, 256, ATT_SMEM>>>(gqkvh);

        gemm_kernel<<<gridH, 256, GEMM_SMEM>>>(
            goh, wph + (size_t)l*HH*HH,
            bp + bo, gx, gt, nullptr, MM, HH, HH, 2);
        ln_kernel<<<MM, 256>>>(gt, g1w + bo, be1 + bo, gx, gxh);

        gemm_kernel<<<gridF, 256, GEMM_SMEM>>>(
            gxh, w1h + (size_t)l*FFF*HH,
            b1 + (size_t)l*FFF, nullptr, nullptr, ghh, MM, FFF, HH, 1);
        gemm_kernel<<<gridH, 256, GEMM_SMEM>>>(
            ghh, w2h + (size_t)l*HH*FFF,
            b2 + bo, gx, gt, nullptr, MM, HH, FFF, 2);
        // final-layer LN writes straight to d_out (skips trailing memcpy)
        ln_kernel<<<MM, 256>>>(gt, g2w + bo, be2 + bo,
                               (l == LL-1) ? (float*)d_out : gx, gxh);
    }
}